// round 9
// baseline (speedup 1.0000x reference)
#include <cuda_runtime.h>
#include <math.h>

// ---------------------------------------------------------------------------
// DiffusionLoss fused single-kernel.
// grid = B * ntri (36) = 144 blocks x 512 threads, all co-resident.
// Bond term: sum_ij wiwj (dp-dg)^2 = [closed form O(N)] - 2*sum_ij wiwj dp*dg
// -> O(N^2) loop computes only wi wj sqrt(dp2*dg2) (packed f32x2, 1 MUFU/pair).
// This round: all global loads COALESCED (contiguous staging into smem), row
// registers + formatted j-tile built from smem.
// ---------------------------------------------------------------------------

#define MAXB 16
#define MAXBLK 64
#define TILE 256
#define NTHR 512
#define NMOM 18

__device__ double   g_part[MAXB][MAXBLK][NMOM];
__device__ unsigned g_cnt[MAXB];
__device__ int      g_ready[MAXB];
__device__ float    g_par[MAXB][15];   // R[9], mu[3], muGT[3]
__device__ double   g_W[MAXB];
__device__ double   g_closed[MAXB];    // closed-form sum_ij wiwj (dp2+dg2)
__device__ double   g_num1[MAXB];
__device__ double   g_bond;            // sum_ij wi wj dp*dg (full matrix)
__device__ unsigned g_done;

__device__ __forceinline__ float fsqrt_approx(float x) {
    float r;
    asm("sqrt.approx.f32 %0, %1;" : "=f"(r) : "f"(x));
    return r;
}

#define PACK_F32X2(out, lo, hi) \
    asm("mov.b64 %0, {%1, %2};" : "=l"(out) : "f"(lo), "f"(hi))
#define UNPACK_F32X2(lo, hi, in) \
    asm("mov.b64 {%0, %1}, %2;" : "=f"(lo), "=f"(hi) : "l"(in))
#define ADD_F32X2(out, a, b) \
    asm("add.rn.f32x2 %0, %1, %2;" : "=l"(out) : "l"(a), "l"(b))
#define FMA_F32X2(d, a, b, c) \
    asm("fma.rn.f32x2 %0, %1, %2, %3;" : "=l"(d) : "l"(a), "l"(b), "l"(c))

// ---------------------------------------------------------------------------
// 3x3 Kabsch solve from moments v[18]; also stores the closed-form term.
// ---------------------------------------------------------------------------
__device__ void kabsch_solve(const double* v, int b)
{
    double W = v[0];
    double invW = 1.0 / W;
    double spw2 = v[1]*v[1] + v[2]*v[2] + v[3]*v[3];
    double sgw2 = v[4]*v[4] + v[5]*v[5] + v[6]*v[6];
    g_closed[b] = 2.0*(W*v[16] - spw2) + 2.0*(W*v[17] - sgw2);

    // mu = GT weighted mean, muGT = pred mean (arg-swap in reference)
    float muGT[3] = { (float)(v[1]*invW), (float)(v[2]*invW), (float)(v[3]*invW) };
    float mu[3]   = { (float)(v[4]*invW), (float)(v[5]*invW), (float)(v[6]*invW) };

    float A[3][3];
    for (int i = 0; i < 3; i++)
        for (int j = 0; j < 3; j++)
            A[i][j] = (float)(v[7 + i*3 + j] - v[1+i]*v[4+j]*invW);

    float detA = A[0][0]*(A[1][1]*A[2][2]-A[1][2]*A[2][1])
               - A[0][1]*(A[1][0]*A[2][2]-A[1][2]*A[2][0])
               + A[0][2]*(A[1][0]*A[2][1]-A[1][1]*A[2][0]);

    float C[3][3];
    for (int i = 0; i < 3; i++)
        for (int j = 0; j < 3; j++) {
            float s = 0.f;
            for (int k = 0; k < 3; k++) s += A[k][i]*A[k][j];
            C[i][j] = s;
        }
    float V[3][3] = {{1,0,0},{0,1,0},{0,0,1}};
#pragma unroll
    for (int sweep = 0; sweep < 6; sweep++) {
#pragma unroll
        for (int p = 0; p < 3; p++)
#pragma unroll
            for (int q = p+1; q < 3; q++) {
                float apq = C[p][q];
                if (apq == 0.f) continue;
                float theta = __fdividef(C[q][q] - C[p][p], 2.f * apq);
                float tt = (theta >= 0.f ? 1.f : -1.f) *
                           __fdividef(1.f, fabsf(theta) + sqrtf(theta*theta + 1.f));
                float c = rsqrtf(tt*tt + 1.f), s = tt * c;
                for (int k = 0; k < 3; k++) {
                    float a = C[k][p], bb = C[k][q];
                    C[k][p] = c*a - s*bb;  C[k][q] = s*a + c*bb;
                }
                for (int k = 0; k < 3; k++) {
                    float a = C[p][k], bb = C[q][k];
                    C[p][k] = c*a - s*bb;  C[q][k] = s*a + c*bb;
                }
                for (int k = 0; k < 3; k++) {
                    float a = V[k][p], bb = V[k][q];
                    V[k][p] = c*a - s*bb;  V[k][q] = s*a + c*bb;
                }
            }
    }
    float eig[3] = { C[0][0], C[1][1], C[2][2] };
    int idx[3] = {0, 1, 2};
    for (int i = 0; i < 2; i++)
        for (int j = i+1; j < 3; j++)
            if (eig[idx[j]] > eig[idx[i]]) { int tmp = idx[i]; idx[i] = idx[j]; idx[j] = tmp; }

    float emax = fmaxf(eig[idx[0]], 0.f);
    float dinv[3];
    for (int i = 0; i < 3; i++) {
        float e = fmaxf(eig[idx[i]], 0.f);
        dinv[i] = (e > 1e-12f * emax && e > 0.f) ? rsqrtf(e) : 0.f;
    }
    if (detA < 0.f) dinv[2] = -dinv[2];

    float T[3][3];
    for (int i = 0; i < 3; i++)
        for (int j = 0; j < 3; j++) {
            float s = 0.f;
            for (int k = 0; k < 3; k++) s += A[i][k] * V[k][idx[j]];
            T[i][j] = s * dinv[j];
        }
    for (int i = 0; i < 3; i++)
        for (int j = 0; j < 3; j++) {
            float s = 0.f;
            for (int k = 0; k < 3; k++) s += T[i][k] * V[j][idx[k]];
            g_par[b][i*3 + j] = s;
        }
    g_par[b][9]  = mu[0];   g_par[b][10] = mu[1];   g_par[b][11] = mu[2];
    g_par[b][12] = muGT[0]; g_par[b][13] = muGT[1]; g_par[b][14] = muGT[2];
    g_W[b] = W;
}

// ---------------------------------------------------------------------------
// Fallback K1 (general shapes): 18-moment reduction + solve.
// ---------------------------------------------------------------------------
__global__ void __launch_bounds__(256)
reduce_solve_kernel(const float* __restrict__ pred,
                    const float* __restrict__ gt,
                    const float* __restrict__ w,
                    int N, int blocksPerB)
{
    const int b   = blockIdx.x / blocksPerB;
    const int blk = blockIdx.x % blocksPerB;
    const int t   = threadIdx.x;
    const float* pb = pred + (size_t)b * N * 3;
    const float* gb = gt   + (size_t)b * N * 3;
    const float* wb = w    + (size_t)b * N;

    float acc[NMOM];
#pragma unroll
    for (int i = 0; i < NMOM; i++) acc[i] = 0.f;
    for (int n = blk * blockDim.x + t; n < N; n += blocksPerB * blockDim.x) {
        float wn = wb[n];
        float px = pb[3*n], py = pb[3*n+1], pz = pb[3*n+2];
        float gx = gb[3*n], gy = gb[3*n+1], gz = gb[3*n+2];
        float wpx = wn*px, wpy = wn*py, wpz = wn*pz;
        acc[0] += wn;
        acc[1] += wpx;  acc[2] += wpy;  acc[3] += wpz;
        acc[4] += wn*gx; acc[5] += wn*gy; acc[6] += wn*gz;
        acc[7] += wpx*gx; acc[8] += wpx*gy; acc[9] += wpx*gz;
        acc[10] += wpy*gx; acc[11] += wpy*gy; acc[12] += wpy*gz;
        acc[13] += wpz*gx; acc[14] += wpz*gy; acc[15] += wpz*gz;
        acc[16] += wpx*px + wpy*py + wpz*pz;
        acc[17] += wn*(gx*gx + gy*gy + gz*gz);
    }
    const unsigned mask = 0xffffffffu;
#pragma unroll
    for (int i = 0; i < NMOM; i++)
        for (int o = 16; o > 0; o >>= 1)
            acc[i] += __shfl_down_sync(mask, acc[i], o);
    __shared__ double sred[8][NMOM];
    int warp = t >> 5, lane = t & 31;
    if (lane == 0)
#pragma unroll
        for (int i = 0; i < NMOM; i++) sred[warp][i] = (double)acc[i];
    __syncthreads();
    if (t != 0) return;
    double v[NMOM];
#pragma unroll
    for (int i = 0; i < NMOM; i++) {
        double s = 0.0;
        for (int wi = 0; wi < 8; wi++) s += sred[wi][i];
        g_part[b][blk][i] = s;
    }
    __threadfence();
    unsigned old = atomicInc(&g_cnt[b], (unsigned)(blocksPerB - 1));
    if (old != (unsigned)(blocksPerB - 1)) return;
    __threadfence();
    double vv[NMOM];
    for (int i = 0; i < NMOM; i++) {
        double s = 0.0;
        for (int k = 0; k < blocksPerB; k++) s += g_part[b][k][i];
        vv[i] = s;
    }
    kabsch_solve(vv, b);
    g_num1[b] = 0.0;
    if (b == 0) g_bond = 0.0;
    __threadfence();
}

// ---------------------------------------------------------------------------
// Fused kernel: 256x256 tiles, 512 threads, coalesced smem staging.
// thread t: rows 4*(t&63)+{0..3} of tile ti, j-eighth (t>>6) of tile tj.
// ---------------------------------------------------------------------------
__global__ void __launch_bounds__(NTHR)
fused_kernel(const float* __restrict__ pred,
             const float* __restrict__ gt,
             const float* __restrict__ w,
             const float* __restrict__ ht,
             float* __restrict__ out,
             int N, int B, int tilesI, int ntri, int precomputed)
{
    const int t  = threadIdx.x;
    const int rp = t & 63;           // row-quad index (64 quads = 256 rows)
    const int jq = t >> 6;           // j eighth 0..7 (32 j's each)
    const int nOff = ntri - tilesI;
    const int blk = blockIdx.x;

    int b, ti, tj;
    bool diag;
    if (blk < B * tilesI) {          // diagonal tiles first
        diag = true;
        b = blk / tilesI;
        ti = tj = blk % tilesI;
    } else {
        diag = false;
        int rem = blk - B * tilesI;
        b = rem / nOff;
        int r2 = rem % nOff;
        ti = 0;
        int rowlen = tilesI - 1;
        while (r2 >= rowlen) { r2 -= rowlen; ti++; rowlen--; }
        tj = ti + 1 + r2;
    }

    const float* pb = pred + (size_t)b * N * 3;
    const float* gb = gt   + (size_t)b * N * 3;
    const float* wb = w    + (size_t)b * N;

    // raw coalesced staging (tile I = rows, tile J = cols)
    __shared__ float rawPI[TILE*3], rawGI[TILE*3], rawWI[TILE];
    __shared__ float rawPJ[TILE*3], rawGJ[TILE*3], rawWJ[TILE];
    // formatted j tile
    __shared__ float4 sA[TILE];   // (pjx, gjx, pjy, gjy)
    __shared__ float4 sZ[TILE];   // (pjz, gjz, pn2j, gn2j)
    __shared__ float  sW[TILE];
    __shared__ double sred[2][NMOM];
    __shared__ double sredp[NTHR/32];
    __shared__ double sreda[2];

    // ---- stage tiles with coalesced LDG ----
    {
        int baseI3 = ti * TILE * 3, baseJ3 = tj * TILE * 3;
        int baseI = ti * TILE, baseJ = tj * TILE;
        int n3 = 3 * N;
#pragma unroll
        for (int idx = t; idx < TILE*3; idx += NTHR) {
            int gi = baseI3 + idx;
            float pv = 0.f, gv = 0.f;
            if (gi < n3) { pv = pb[gi]; gv = gb[gi]; }
            rawPI[idx] = pv; rawGI[idx] = gv;
        }
        if (t < TILE) {
            int gi = baseI + t;
            rawWI[t] = (gi < N) ? wb[gi] : 0.f;
        }
        if (!diag) {
#pragma unroll
            for (int idx = t; idx < TILE*3; idx += NTHR) {
                int gi = baseJ3 + idx;
                float pv = 0.f, gv = 0.f;
                if (gi < n3) { pv = pb[gi]; gv = gb[gi]; }
                rawPJ[idx] = pv; rawGJ[idx] = gv;
            }
            if (t < TILE) {
                int gi = baseJ + t;
                rawWJ[t] = (gi < N) ? wb[gi] : 0.f;
            }
        }
    }
    __syncthreads();

    const float* RPJ = diag ? rawPI : rawPJ;
    const float* RGJ = diag ? rawGI : rawGJ;
    const float* RWJ = diag ? rawWI : rawWJ;

    // ---- format j tile from smem (threads 0..255) ----
    if (t < TILE) {
        float px = RPJ[3*t], py = RPJ[3*t+1], pz = RPJ[3*t+2];
        float gx = RGJ[3*t], gy = RGJ[3*t+1], gz = RGJ[3*t+2];
        sA[t] = make_float4(px, gx, py, gy);
        sZ[t] = make_float4(pz, gz, px*px+py*py+pz*pz, gx*gx+gy*gy+gz*gz);
        sW[t] = RWJ[t];
    }

    // ---- load four i-rows into registers from smem ----
    float pxr[4], pyr[4], pzr[4], gxr[4], gyr[4], gzr[4], wr[4];
#pragma unroll
    for (int r = 0; r < 4; r++) {
        int li = 4*rp + r;
        pxr[r] = rawPI[3*li];   pyr[r] = rawPI[3*li+1]; pzr[r] = rawPI[3*li+2];
        gxr[r] = rawGI[3*li];   gyr[r] = rawGI[3*li+1]; gzr[r] = rawGI[3*li+2];
        wr[r]  = rawWI[li];
    }

    unsigned long long ax[4], ay[4], az[4], bs[4];
#pragma unroll
    for (int r = 0; r < 4; r++) {
        PACK_F32X2(ax[r], -2.f*pxr[r], -2.f*gxr[r]);
        PACK_F32X2(ay[r], -2.f*pyr[r], -2.f*gyr[r]);
        PACK_F32X2(az[r], -2.f*pzr[r], -2.f*gzr[r]);
        PACK_F32X2(bs[r], pxr[r]*pxr[r]+pyr[r]*pyr[r]+pzr[r]*pzr[r],
                          gxr[r]*gxr[r]+gyr[r]*gyr[r]+gzr[r]*gzr[r]);
    }

    const unsigned mask = 0xffffffffu;
    int warp = t >> 5, lane = t & 31;

    // ---- stats partial (diagonal blocks; threads t<64 own the 256 rows) ----
    if (diag && !precomputed && t < 64) {
        float acc[NMOM];
#pragma unroll
        for (int i = 0; i < NMOM; i++) acc[i] = 0.f;
#pragma unroll
        for (int r = 0; r < 4; r++) {
            float wn = wr[r];
            float px = pxr[r], py = pyr[r], pz = pzr[r];
            float gx = gxr[r], gy = gyr[r], gz = gzr[r];
            float wpx = wn*px, wpy = wn*py, wpz = wn*pz;
            acc[0] += wn;
            acc[1] += wpx;  acc[2] += wpy;  acc[3] += wpz;
            acc[4] += wn*gx; acc[5] += wn*gy; acc[6] += wn*gz;
            acc[7] += wpx*gx; acc[8] += wpx*gy; acc[9] += wpx*gz;
            acc[10] += wpy*gx; acc[11] += wpy*gy; acc[12] += wpy*gz;
            acc[13] += wpz*gx; acc[14] += wpz*gy; acc[15] += wpz*gz;
            acc[16] += wpx*px + wpy*py + wpz*pz;
            acc[17] += wn*(gx*gx + gy*gy + gz*gz);
        }
#pragma unroll
        for (int i = 0; i < NMOM; i++)
            for (int o = 16; o > 0; o >>= 1)
                acc[i] += __shfl_down_sync(mask, acc[i], o);
        if (lane == 0)
#pragma unroll
            for (int i = 0; i < NMOM; i++) sred[warp][i] = (double)acc[i];
    }
    __syncthreads();   // sA/sZ/sW + sred visible

    if (diag && !precomputed && t == 0) {
#pragma unroll
        for (int i = 0; i < NMOM; i++)
            g_part[b][ti][i] = sred[0][i] + sred[1][i];
        __threadfence();
        unsigned old = atomicInc(&g_cnt[b], (unsigned)(tilesI - 1));
        if (old == (unsigned)(tilesI - 1)) {
            __threadfence();
            double vv[NMOM];
            for (int i = 0; i < NMOM; i++) {
                double s = 0.0;
                for (int k = 0; k < tilesI; k++) s += g_part[b][k][i];
                vv[i] = s;
            }
            kabsch_solve(vv, b);
            __threadfence();
            atomicExch(&g_ready[b], 1);
        }
    }

    // ---- cross-term loop: acc_r += wj * sqrt(dp2*dg2), 4 rows x 32 j ----
    float accr[4] = {0.f, 0.f, 0.f, 0.f};
    const int kbase = jq * 32;
#pragma unroll 4
    for (int kk = 0; kk < 32; kk++) {
        int k = kbase + kk;
        ulonglong2 A = *reinterpret_cast<const ulonglong2*>(&sA[k]);
        ulonglong2 Z = *reinterpret_cast<const ulonglong2*>(&sZ[k]);
        float wj = sW[k];
#pragma unroll
        for (int r = 0; r < 4; r++) {
            unsigned long long c;
            FMA_F32X2(c, az[r], Z.x, Z.y);   // -2z*zj + (pn2j,gn2j)
            FMA_F32X2(c, ay[r], A.y, c);
            FMA_F32X2(c, ax[r], A.x, c);
            ADD_F32X2(c, c, bs[r]);          // -> (dp2, dg2)
            float dp2, dg2;
            UNPACK_F32X2(dp2, dg2, c);
            float prod = fmaxf(dp2 * dg2, 0.f);
            float s = fsqrt_approx(prod);    // = dp*dg
            accr[r] = fmaf(wj, s, accr[r]);
        }
    }

    double tot = (double)(accr[0]*wr[0]) + (double)(accr[1]*wr[1])
               + (double)(accr[2]*wr[2]) + (double)(accr[3]*wr[3]);
    if (!diag) tot *= 2.0;           // symmetry
    for (int o = 16; o > 0; o >>= 1)
        tot += __shfl_down_sync(mask, tot, o);
    if (lane == 0) sredp[warp] = tot;

    // ---- fused alignment loss (diagonal blocks; threads t<64) ----
    if (diag) {
        if (!precomputed && t == 0) {
            int r;
            do {
                asm volatile("ld.acquire.gpu.b32 %0, [%1];"
                             : "=r"(r) : "l"(&g_ready[b]) : "memory");
            } while (r == 0);
        }
        __syncthreads();
        if (t < 64) {
            float R00 = g_par[b][0], R01 = g_par[b][1], R02 = g_par[b][2];
            float R10 = g_par[b][3], R11 = g_par[b][4], R12 = g_par[b][5];
            float R20 = g_par[b][6], R21 = g_par[b][7], R22 = g_par[b][8];
            float mux = g_par[b][9],  muy = g_par[b][10], muz = g_par[b][11];
            float mgx = g_par[b][12], mgy = g_par[b][13], mgz = g_par[b][14];

            float alf = 0.f;
#pragma unroll
            for (int r = 0; r < 4; r++) {
                float gx = gxr[r] - mux, gy = gyr[r] - muy, gz = gzr[r] - muz;
                float axv = R00*gx + R01*gy + R02*gz + mgx;
                float ayv = R10*gx + R11*gy + R12*gz + mgy;
                float azv = R20*gx + R21*gy + R22*gz + mgz;
                float dx = pxr[r] - axv, dy = pyr[r] - ayv, dz = pzr[r] - azv;
                alf += wr[r] * fsqrt_approx(dx*dx + dy*dy + dz*dz);
            }
            double al = (double)alf;
            for (int o = 16; o > 0; o >>= 1)
                al += __shfl_down_sync(mask, al, o);
            if (lane == 0) sreda[warp] = al;
        }
        __syncthreads();
        if (t == 0)
            atomicAdd(&g_num1[b], sreda[0] + sreda[1]);
    }
    __syncthreads();

    // ---- block totals + global completion ----
    if (t == 0) {
        double s = 0.0;
        for (int wi = 0; wi < NTHR/32; wi++) s += sredp[wi];
        atomicAdd(&g_bond, s);
        __threadfence();
        unsigned old = atomicInc(&g_done, (unsigned)(gridDim.x - 1));
        if (old == (unsigned)(gridDim.x - 1)) {
            __threadfence();
            double sw = 0.0, sw2 = 0.0, sn = 0.0, scl = 0.0;
            for (int bb = 0; bb < B; bb++) {
                double W = g_W[bb];
                sw += W; sw2 += W * W; sn += g_num1[bb]; scl += g_closed[bb];
            }
            double loss = sn / sw + (scl - 2.0 * g_bond) / sw2;
            for (int bb = 0; bb < B; bb++) {
                double h = (double)ht[bb];
                out[bb] = (float)(((h*h + 256.0) / ((h + 16.0) * (h + 16.0))) * loss);
            }
            g_bond = 0.0;
            for (int bb = 0; bb < B; bb++) { g_num1[bb] = 0.0; g_ready[bb] = 0; }
            __threadfence();
        }
    }
}

extern "C" void kernel_launch(void* const* d_in, const int* in_sizes, int n_in,
                              void* d_out, int out_size)
{
    const float* pred = (const float*)d_in[0];
    const float* gt   = (const float*)d_in[1];
    const float* ht   = (const float*)d_in[2];
    const float* w    = (const float*)d_in[3];
    int B = in_sizes[2];
    int N = in_sizes[3] / B;

    int tilesI = (N + TILE - 1) / TILE;
    int ntri = tilesI * (tilesI + 1) / 2;
    int grid = B * ntri;

    if (grid <= 148 && tilesI <= MAXBLK && B <= MAXB) {
        fused_kernel<<<grid, NTHR>>>(pred, gt, w, ht, (float*)d_out,
                                     N, B, tilesI, ntri, 0);
    } else {
        int blocksPerB = (N + 255) / 256;
        if (blocksPerB > MAXBLK) blocksPerB = MAXBLK;
        reduce_solve_kernel<<<B * blocksPerB, 256>>>(pred, gt, w, N, blocksPerB);
        fused_kernel<<<grid, NTHR>>>(pred, gt, w, ht, (float*)d_out,
                                     N, B, tilesI, ntri, 1);
    }
}

// round 10
// speedup vs baseline: 1.6633x; 1.6633x over previous
#include <cuda_runtime.h>
#include <math.h>

// ---------------------------------------------------------------------------
// DiffusionLoss fused single-kernel. grid = B*ntri (144) x 512, co-resident.
// Bond: sum_ij wiwj (dp-dg)^2 = [closed form O(N)] - 2*sum_ij wiwj dp*dg
//   -> O(N^2) loop computes only wi wj sqrt(|dp2*dg2|) (packed f32x2, 1 MUFU).
// Cycle-focused round (effective clock ~0.5GHz): parallel moment sum, float
// reductions (no DADD chains), float final combine, fabs-folded sqrt.
// ---------------------------------------------------------------------------

#define MAXB 16
#define MAXBLK 64
#define TILE 256
#define NTHR 512
#define NMOM 18

__device__ double   g_part[MAXB][MAXBLK][NMOM];
__device__ unsigned g_cnt[MAXB];
__device__ int      g_ready[MAXB];
__device__ float    g_par[MAXB][15];   // R[9], mu[3], muGT[3]
__device__ double   g_W[MAXB];
__device__ double   g_closed[MAXB];    // closed-form sum_ij wiwj (dp2+dg2)
__device__ double   g_num1[MAXB];
__device__ double   g_bond;            // sum_ij wi wj dp*dg (full matrix)
__device__ unsigned g_done;

__device__ __forceinline__ float fsqrt_approx(float x) {
    float r;
    asm("sqrt.approx.f32 %0, %1;" : "=f"(r) : "f"(x));
    return r;
}

#define PACK_F32X2(out, lo, hi) \
    asm("mov.b64 %0, {%1, %2};" : "=l"(out) : "f"(lo), "f"(hi))
#define UNPACK_F32X2(lo, hi, in) \
    asm("mov.b64 {%0, %1}, %2;" : "=f"(lo), "=f"(hi) : "l"(in))
#define ADD_F32X2(out, a, b) \
    asm("add.rn.f32x2 %0, %1, %2;" : "=l"(out) : "l"(a), "l"(b))
#define FMA_F32X2(d, a, b, c) \
    asm("fma.rn.f32x2 %0, %1, %2, %3;" : "=l"(d) : "l"(a), "l"(b), "l"(c))

// ---------------------------------------------------------------------------
// 3x3 Kabsch solve from moments v[18]; also stores the closed-form term.
// ---------------------------------------------------------------------------
__device__ void kabsch_solve(const double* v, int b)
{
    double W = v[0];
    double invW = 1.0 / W;
    double spw2 = v[1]*v[1] + v[2]*v[2] + v[3]*v[3];
    double sgw2 = v[4]*v[4] + v[5]*v[5] + v[6]*v[6];
    g_closed[b] = 2.0*(W*v[16] - spw2) + 2.0*(W*v[17] - sgw2);

    // mu = GT weighted mean, muGT = pred mean (arg-swap in reference)
    float muGT[3] = { (float)(v[1]*invW), (float)(v[2]*invW), (float)(v[3]*invW) };
    float mu[3]   = { (float)(v[4]*invW), (float)(v[5]*invW), (float)(v[6]*invW) };

    float A[3][3];
    for (int i = 0; i < 3; i++)
        for (int j = 0; j < 3; j++)
            A[i][j] = (float)(v[7 + i*3 + j] - v[1+i]*v[4+j]*invW);

    float detA = A[0][0]*(A[1][1]*A[2][2]-A[1][2]*A[2][1])
               - A[0][1]*(A[1][0]*A[2][2]-A[1][2]*A[2][0])
               + A[0][2]*(A[1][0]*A[2][1]-A[1][1]*A[2][0]);

    float C[3][3];
    for (int i = 0; i < 3; i++)
        for (int j = 0; j < 3; j++) {
            float s = 0.f;
            for (int k = 0; k < 3; k++) s += A[k][i]*A[k][j];
            C[i][j] = s;
        }
    float V[3][3] = {{1,0,0},{0,1,0},{0,0,1}};
#pragma unroll
    for (int sweep = 0; sweep < 4; sweep++) {
#pragma unroll
        for (int p = 0; p < 3; p++)
#pragma unroll
            for (int q = p+1; q < 3; q++) {
                float apq = C[p][q];
                if (apq == 0.f) continue;
                float theta = __fdividef(C[q][q] - C[p][p], 2.f * apq);
                float tt = (theta >= 0.f ? 1.f : -1.f) *
                           __fdividef(1.f, fabsf(theta) + sqrtf(theta*theta + 1.f));
                float c = rsqrtf(tt*tt + 1.f), s = tt * c;
                for (int k = 0; k < 3; k++) {
                    float a = C[k][p], bb = C[k][q];
                    C[k][p] = c*a - s*bb;  C[k][q] = s*a + c*bb;
                }
                for (int k = 0; k < 3; k++) {
                    float a = C[p][k], bb = C[q][k];
                    C[p][k] = c*a - s*bb;  C[q][k] = s*a + c*bb;
                }
                for (int k = 0; k < 3; k++) {
                    float a = V[k][p], bb = V[k][q];
                    V[k][p] = c*a - s*bb;  V[k][q] = s*a + c*bb;
                }
            }
    }
    float eig[3] = { C[0][0], C[1][1], C[2][2] };
    int idx[3] = {0, 1, 2};
    for (int i = 0; i < 2; i++)
        for (int j = i+1; j < 3; j++)
            if (eig[idx[j]] > eig[idx[i]]) { int tmp = idx[i]; idx[i] = idx[j]; idx[j] = tmp; }

    float emax = fmaxf(eig[idx[0]], 0.f);
    float dinv[3];
    for (int i = 0; i < 3; i++) {
        float e = fmaxf(eig[idx[i]], 0.f);
        dinv[i] = (e > 1e-12f * emax && e > 0.f) ? rsqrtf(e) : 0.f;
    }
    if (detA < 0.f) dinv[2] = -dinv[2];

    float T[3][3];
    for (int i = 0; i < 3; i++)
        for (int j = 0; j < 3; j++) {
            float s = 0.f;
            for (int k = 0; k < 3; k++) s += A[i][k] * V[k][idx[j]];
            T[i][j] = s * dinv[j];
        }
    for (int i = 0; i < 3; i++)
        for (int j = 0; j < 3; j++) {
            float s = 0.f;
            for (int k = 0; k < 3; k++) s += T[i][k] * V[j][idx[k]];
            g_par[b][i*3 + j] = s;
        }
    g_par[b][9]  = mu[0];   g_par[b][10] = mu[1];   g_par[b][11] = mu[2];
    g_par[b][12] = muGT[0]; g_par[b][13] = muGT[1]; g_par[b][14] = muGT[2];
    g_W[b] = W;
}

// ---------------------------------------------------------------------------
// Fallback K1 (general shapes): 18-moment reduction + solve.
// ---------------------------------------------------------------------------
__global__ void __launch_bounds__(256)
reduce_solve_kernel(const float* __restrict__ pred,
                    const float* __restrict__ gt,
                    const float* __restrict__ w,
                    int N, int blocksPerB)
{
    const int b   = blockIdx.x / blocksPerB;
    const int blk = blockIdx.x % blocksPerB;
    const int t   = threadIdx.x;
    const float* pb = pred + (size_t)b * N * 3;
    const float* gb = gt   + (size_t)b * N * 3;
    const float* wb = w    + (size_t)b * N;

    float acc[NMOM];
#pragma unroll
    for (int i = 0; i < NMOM; i++) acc[i] = 0.f;
    for (int n = blk * blockDim.x + t; n < N; n += blocksPerB * blockDim.x) {
        float wn = wb[n];
        float px = pb[3*n], py = pb[3*n+1], pz = pb[3*n+2];
        float gx = gb[3*n], gy = gb[3*n+1], gz = gb[3*n+2];
        float wpx = wn*px, wpy = wn*py, wpz = wn*pz;
        acc[0] += wn;
        acc[1] += wpx;  acc[2] += wpy;  acc[3] += wpz;
        acc[4] += wn*gx; acc[5] += wn*gy; acc[6] += wn*gz;
        acc[7] += wpx*gx; acc[8] += wpx*gy; acc[9] += wpx*gz;
        acc[10] += wpy*gx; acc[11] += wpy*gy; acc[12] += wpy*gz;
        acc[13] += wpz*gx; acc[14] += wpz*gy; acc[15] += wpz*gz;
        acc[16] += wpx*px + wpy*py + wpz*pz;
        acc[17] += wn*(gx*gx + gy*gy + gz*gz);
    }
    const unsigned mask = 0xffffffffu;
#pragma unroll
    for (int i = 0; i < NMOM; i++)
        for (int o = 16; o > 0; o >>= 1)
            acc[i] += __shfl_down_sync(mask, acc[i], o);
    __shared__ float sred[8][NMOM];
    int warp = t >> 5, lane = t & 31;
    if (lane == 0)
#pragma unroll
        for (int i = 0; i < NMOM; i++) sred[warp][i] = acc[i];
    __syncthreads();
    if (t != 0) return;
    double v[NMOM];
#pragma unroll
    for (int i = 0; i < NMOM; i++) {
        float s = 0.f;
        for (int wi = 0; wi < 8; wi++) s += sred[wi][i];
        g_part[b][blk][i] = (double)s;
    }
    __threadfence();
    unsigned old = atomicInc(&g_cnt[b], (unsigned)(blocksPerB - 1));
    if (old != (unsigned)(blocksPerB - 1)) return;
    __threadfence();
    double vv[NMOM];
    for (int i = 0; i < NMOM; i++) {
        double s = 0.0;
        for (int k = 0; k < blocksPerB; k++) s += g_part[b][k][i];
        vv[i] = s;
    }
    kabsch_solve(vv, b);
    g_num1[b] = 0.0;
    if (b == 0) g_bond = 0.0;
    __threadfence();
}

// ---------------------------------------------------------------------------
// Fused kernel: 256x256 tiles, 512 threads, coalesced smem staging.
// thread t: rows 4*(t&63)+{0..3} of tile ti, j-eighth (t>>6) of tile tj.
// ---------------------------------------------------------------------------
__global__ void __launch_bounds__(NTHR)
fused_kernel(const float* __restrict__ pred,
             const float* __restrict__ gt,
             const float* __restrict__ w,
             const float* __restrict__ ht,
             float* __restrict__ out,
             int N, int B, int tilesI, int ntri, int precomputed)
{
    const int t  = threadIdx.x;
    const int rp = t & 63;           // row-quad index (64 quads = 256 rows)
    const int jq = t >> 6;           // j eighth 0..7 (32 j's each)
    const int nOff = ntri - tilesI;
    const int blk = blockIdx.x;

    int b, ti, tj;
    bool diag;
    if (blk < B * tilesI) {          // diagonal tiles first
        diag = true;
        b = blk / tilesI;
        ti = tj = blk % tilesI;
    } else {
        diag = false;
        int rem = blk - B * tilesI;
        b = rem / nOff;
        int r2 = rem % nOff;
        ti = 0;
        int rowlen = tilesI - 1;
        while (r2 >= rowlen) { r2 -= rowlen; ti++; rowlen--; }
        tj = ti + 1 + r2;
    }

    const float* pb = pred + (size_t)b * N * 3;
    const float* gb = gt   + (size_t)b * N * 3;
    const float* wb = w    + (size_t)b * N;

    __shared__ float rawPI[TILE*3], rawGI[TILE*3], rawWI[TILE];
    __shared__ float rawPJ[TILE*3], rawGJ[TILE*3], rawWJ[TILE];
    __shared__ float4 sA[TILE];   // (pjx, gjx, pjy, gjy)
    __shared__ float4 sZ[TILE];   // (pjz, gjz, pn2j, gn2j)
    __shared__ float  sW[TILE];
    __shared__ float  sredM[2][NMOM];
    __shared__ float  sredp[NTHR/32];
    __shared__ float  sreda[2];
    __shared__ double svv[NMOM];
    __shared__ int    sIsLast;

    // ---- stage tiles with coalesced LDG ----
    {
        int baseI3 = ti * TILE * 3, baseJ3 = tj * TILE * 3;
        int baseI = ti * TILE, baseJ = tj * TILE;
        int n3 = 3 * N;
#pragma unroll
        for (int idx = t; idx < TILE*3; idx += NTHR) {
            int gi = baseI3 + idx;
            float pv = 0.f, gv = 0.f;
            if (gi < n3) { pv = pb[gi]; gv = gb[gi]; }
            rawPI[idx] = pv; rawGI[idx] = gv;
        }
        if (t < TILE) {
            int gi = baseI + t;
            rawWI[t] = (gi < N) ? wb[gi] : 0.f;
        }
        if (!diag) {
#pragma unroll
            for (int idx = t; idx < TILE*3; idx += NTHR) {
                int gi = baseJ3 + idx;
                float pv = 0.f, gv = 0.f;
                if (gi < n3) { pv = pb[gi]; gv = gb[gi]; }
                rawPJ[idx] = pv; rawGJ[idx] = gv;
            }
            if (t < TILE) {
                int gi = baseJ + t;
                rawWJ[t] = (gi < N) ? wb[gi] : 0.f;
            }
        }
    }
    __syncthreads();

    const float* RPJ = diag ? rawPI : rawPJ;
    const float* RGJ = diag ? rawGI : rawGJ;
    const float* RWJ = diag ? rawWI : rawWJ;

    // ---- format j tile from smem (threads 0..255) ----
    if (t < TILE) {
        float px = RPJ[3*t], py = RPJ[3*t+1], pz = RPJ[3*t+2];
        float gx = RGJ[3*t], gy = RGJ[3*t+1], gz = RGJ[3*t+2];
        sA[t] = make_float4(px, gx, py, gy);
        sZ[t] = make_float4(pz, gz, px*px+py*py+pz*pz, gx*gx+gy*gy+gz*gz);
        sW[t] = RWJ[t];
    }

    // ---- load four i-rows into registers from smem ----
    float pxr[4], pyr[4], pzr[4], gxr[4], gyr[4], gzr[4], wr[4];
#pragma unroll
    for (int r = 0; r < 4; r++) {
        int li = 4*rp + r;
        pxr[r] = rawPI[3*li];   pyr[r] = rawPI[3*li+1]; pzr[r] = rawPI[3*li+2];
        gxr[r] = rawGI[3*li];   gyr[r] = rawGI[3*li+1]; gzr[r] = rawGI[3*li+2];
        wr[r]  = rawWI[li];
    }

    unsigned long long ax[4], ay[4], az[4], bs[4];
#pragma unroll
    for (int r = 0; r < 4; r++) {
        PACK_F32X2(ax[r], -2.f*pxr[r], -2.f*gxr[r]);
        PACK_F32X2(ay[r], -2.f*pyr[r], -2.f*gyr[r]);
        PACK_F32X2(az[r], -2.f*pzr[r], -2.f*gzr[r]);
        PACK_F32X2(bs[r], pxr[r]*pxr[r]+pyr[r]*pyr[r]+pzr[r]*pzr[r],
                          gxr[r]*gxr[r]+gyr[r]*gyr[r]+gzr[r]*gzr[r]);
    }

    const unsigned mask = 0xffffffffu;
    int warp = t >> 5, lane = t & 31;

    // ---- stats partial (diagonal blocks; threads t<64 own the 256 rows) ----
    if (diag && !precomputed) {
        if (t < 64) {
            float acc[NMOM];
#pragma unroll
            for (int i = 0; i < NMOM; i++) acc[i] = 0.f;
#pragma unroll
            for (int r = 0; r < 4; r++) {
                float wn = wr[r];
                float px = pxr[r], py = pyr[r], pz = pzr[r];
                float gx = gxr[r], gy = gyr[r], gz = gzr[r];
                float wpx = wn*px, wpy = wn*py, wpz = wn*pz;
                acc[0] += wn;
                acc[1] += wpx;  acc[2] += wpy;  acc[3] += wpz;
                acc[4] += wn*gx; acc[5] += wn*gy; acc[6] += wn*gz;
                acc[7] += wpx*gx; acc[8] += wpx*gy; acc[9] += wpx*gz;
                acc[10] += wpy*gx; acc[11] += wpy*gy; acc[12] += wpy*gz;
                acc[13] += wpz*gx; acc[14] += wpz*gy; acc[15] += wpz*gz;
                acc[16] += wpx*px + wpy*py + wpz*pz;
                acc[17] += wn*(gx*gx + gy*gy + gz*gz);
            }
#pragma unroll
            for (int i = 0; i < NMOM; i++)
                for (int o = 16; o > 0; o >>= 1)
                    acc[i] += __shfl_down_sync(mask, acc[i], o);
            if (lane == 0)
#pragma unroll
                for (int i = 0; i < NMOM; i++) sredM[warp][i] = acc[i];
        }
        __syncthreads();   // sredM + sA/sZ/sW visible
        if (t == 0) {
#pragma unroll
            for (int i = 0; i < NMOM; i++)
                g_part[b][ti][i] = (double)(sredM[0][i] + sredM[1][i]);
            __threadfence();
            unsigned old = atomicInc(&g_cnt[b], (unsigned)(tilesI - 1));
            sIsLast = (old == (unsigned)(tilesI - 1));
        }
        __syncthreads();
        if (sIsLast) {
            // warp 0: parallel moment gather (MLP), then t0 solves
            if (t < NMOM) {
                double s = 0.0;
                for (int k = 0; k < tilesI; k++) s += g_part[b][k][t];
                svv[t] = s;
            }
            __syncwarp(mask);
            if (t == 0) {
                kabsch_solve(svv, b);
                __threadfence();
                atomicExch(&g_ready[b], 1);
            }
        }
    } else {
        __syncthreads();   // sA/sZ/sW visible
    }

    // ---- cross-term loop: acc_r += wj * sqrt(|dp2*dg2|), 4 rows x 32 j ----
    float accr[4] = {0.f, 0.f, 0.f, 0.f};
    const int kbase = jq * 32;
#pragma unroll 4
    for (int kk = 0; kk < 32; kk++) {
        int k = kbase + kk;
        ulonglong2 A = *reinterpret_cast<const ulonglong2*>(&sA[k]);
        ulonglong2 Z = *reinterpret_cast<const ulonglong2*>(&sZ[k]);
        float wj = sW[k];
#pragma unroll
        for (int r = 0; r < 4; r++) {
            unsigned long long c;
            FMA_F32X2(c, az[r], Z.x, Z.y);   // -2z*zj + (pn2j,gn2j)
            FMA_F32X2(c, ay[r], A.y, c);
            FMA_F32X2(c, ax[r], A.x, c);
            ADD_F32X2(c, c, bs[r]);          // -> (dp2, dg2)
            float dp2, dg2;
            UNPACK_F32X2(dp2, dg2, c);
            float s = fsqrt_approx(fabsf(dp2 * dg2));  // |.| folds into MUFU
            accr[r] = fmaf(wj, s, accr[r]);
        }
    }

    float tot = accr[0]*wr[0] + accr[1]*wr[1] + accr[2]*wr[2] + accr[3]*wr[3];
    if (!diag) tot *= 2.f;           // symmetry
    for (int o = 16; o > 0; o >>= 1)
        tot += __shfl_down_sync(mask, tot, o);
    if (lane == 0) sredp[warp] = tot;

    // ---- fused alignment loss (diagonal blocks; threads t<64) ----
    if (diag) {
        if (!precomputed && t == 0) {
            int r;
            do {
                asm volatile("ld.acquire.gpu.b32 %0, [%1];"
                             : "=r"(r) : "l"(&g_ready[b]) : "memory");
            } while (r == 0);
        }
        __syncthreads();
        if (t < 64) {
            float R00 = g_par[b][0], R01 = g_par[b][1], R02 = g_par[b][2];
            float R10 = g_par[b][3], R11 = g_par[b][4], R12 = g_par[b][5];
            float R20 = g_par[b][6], R21 = g_par[b][7], R22 = g_par[b][8];
            float mux = g_par[b][9],  muy = g_par[b][10], muz = g_par[b][11];
            float mgx = g_par[b][12], mgy = g_par[b][13], mgz = g_par[b][14];

            float alf = 0.f;
#pragma unroll
            for (int r = 0; r < 4; r++) {
                float gx = gxr[r] - mux, gy = gyr[r] - muy, gz = gzr[r] - muz;
                float axv = R00*gx + R01*gy + R02*gz + mgx;
                float ayv = R10*gx + R11*gy + R12*gz + mgy;
                float azv = R20*gx + R21*gy + R22*gz + mgz;
                float dx = pxr[r] - axv, dy = pyr[r] - ayv, dz = pzr[r] - azv;
                alf += wr[r] * fsqrt_approx(dx*dx + dy*dy + dz*dz);
            }
            for (int o = 16; o > 0; o >>= 1)
                alf += __shfl_down_sync(mask, alf, o);
            if (lane == 0) sreda[warp] = alf;
        }
    }
    __syncthreads();

    // ---- block totals + global completion ----
    if (t == 0) {
        float s = 0.f;
        for (int wi = 0; wi < NTHR/32; wi++) s += sredp[wi];
        atomicAdd(&g_bond, (double)s);
        if (diag)
            atomicAdd(&g_num1[b], (double)(sreda[0] + sreda[1]));
        __threadfence();
        unsigned old = atomicInc(&g_done, (unsigned)(gridDim.x - 1));
        if (old == (unsigned)(gridDim.x - 1)) {
            __threadfence();
            float sw = 0.f, sw2 = 0.f, sn = 0.f, scl = 0.f;
            for (int bb = 0; bb < B; bb++) {
                float W = (float)g_W[bb];
                sw += W; sw2 += W * W;
                sn += (float)g_num1[bb]; scl += (float)g_closed[bb];
            }
            float bond = (float)g_bond;
            float loss = __fdividef(sn, sw)
                       + __fdividef(scl - 2.f * bond, sw2);
            for (int bb = 0; bb < B; bb++) {
                float h = __ldg(&ht[bb]);
                float d = (h + 16.f);
                out[bb] = (h*h + 256.f) * __fdividef(loss, d*d);
            }
            g_bond = 0.0;
            for (int bb = 0; bb < B; bb++) { g_num1[bb] = 0.0; g_ready[bb] = 0; }
            __threadfence();
        }
    }
}

extern "C" void kernel_launch(void* const* d_in, const int* in_sizes, int n_in,
                              void* d_out, int out_size)
{
    const float* pred = (const float*)d_in[0];
    const float* gt   = (const float*)d_in[1];
    const float* ht   = (const float*)d_in[2];
    const float* w    = (const float*)d_in[3];
    int B = in_sizes[2];
    int N = in_sizes[3] / B;

    int tilesI = (N + TILE - 1) / TILE;
    int ntri = tilesI * (tilesI + 1) / 2;
    int grid = B * ntri;

    if (grid <= 148 && tilesI <= MAXBLK && B <= MAXB) {
        fused_kernel<<<grid, NTHR>>>(pred, gt, w, ht, (float*)d_out,
                                     N, B, tilesI, ntri, 0);
    } else {
        int blocksPerB = (N + 255) / 256;
        if (blocksPerB > MAXBLK) blocksPerB = MAXBLK;
        reduce_solve_kernel<<<B * blocksPerB, 256>>>(pred, gt, w, N, blocksPerB);
        fused_kernel<<<grid, NTHR>>>(pred, gt, w, ht, (float*)d_out,
                                     N, B, tilesI, ntri, 1);
    }
}

// round 11
// speedup vs baseline: 1.8340x; 1.1026x over previous
#include <cuda_runtime.h>
#include <math.h>

// ---------------------------------------------------------------------------
// DiffusionLoss fused single-kernel with dedicated solver blocks.
// grid = B*ntri + B = 148 blocks x 512 threads (exactly one wave).
//   - diag blocks: stage tile, stats partial -> g_cnt, bond loop, then
//     alignment loss (flag set by solver DURING their bond work).
//   - B solver blocks: spin on g_cnt, gather moments, 3x3 Kabsch solve,
//     release g_ready. Runs CONCURRENTLY with bond compute.
//   - off-diag blocks: stage 2 tiles, bond loop only.
// Bond: sum_ij wiwj (dp-dg)^2 = [closed form O(N)] - 2*sum_ij wiwj dp*dg
//   -> O(N^2) loop computes only wi wj sqrt(|dp2*dg2|) (packed f32x2, 1 MUFU).
// All reductions float; doubles only in cross-block accumulators.
// ---------------------------------------------------------------------------

#define MAXB 16
#define MAXBLK 64
#define TILE 256
#define NTHR 512
#define NMOM 18

__device__ double   g_part[MAXB][MAXBLK][NMOM];
__device__ unsigned g_cnt[MAXB];       // stats arrivals (reset by solver)
__device__ int      g_ready[MAXB];     // solve-done flag (reset by combiner)
__device__ float    g_par[MAXB][15];   // R[9], mu[3], muGT[3]
__device__ double   g_W[MAXB];
__device__ double   g_closed[MAXB];
__device__ double   g_num1[MAXB];
__device__ double   g_bond;
__device__ unsigned g_done;

__device__ __forceinline__ float fsqrt_approx(float x) {
    float r;
    asm("sqrt.approx.f32 %0, %1;" : "=f"(r) : "f"(x));
    return r;
}

#define PACK_F32X2(out, lo, hi) \
    asm("mov.b64 %0, {%1, %2};" : "=l"(out) : "f"(lo), "f"(hi))
#define UNPACK_F32X2(lo, hi, in) \
    asm("mov.b64 {%0, %1}, %2;" : "=f"(lo), "=f"(hi) : "l"(in))
#define ADD_F32X2(out, a, b) \
    asm("add.rn.f32x2 %0, %1, %2;" : "=l"(out) : "l"(a), "l"(b))
#define FMA_F32X2(d, a, b, c) \
    asm("fma.rn.f32x2 %0, %1, %2, %3;" : "=l"(d) : "l"(a), "l"(b), "l"(c))

// ---------------------------------------------------------------------------
// 3x3 Kabsch solve from moments v[18]; also stores the closed-form term.
// ---------------------------------------------------------------------------
__device__ void kabsch_solve(const double* v, int b)
{
    double W = v[0];
    double invW = 1.0 / W;
    double spw2 = v[1]*v[1] + v[2]*v[2] + v[3]*v[3];
    double sgw2 = v[4]*v[4] + v[5]*v[5] + v[6]*v[6];
    g_closed[b] = 2.0*(W*v[16] - spw2) + 2.0*(W*v[17] - sgw2);

    // mu = GT weighted mean, muGT = pred mean (arg-swap in reference)
    float muGT[3] = { (float)(v[1]*invW), (float)(v[2]*invW), (float)(v[3]*invW) };
    float mu[3]   = { (float)(v[4]*invW), (float)(v[5]*invW), (float)(v[6]*invW) };

    float A[3][3];
    for (int i = 0; i < 3; i++)
        for (int j = 0; j < 3; j++)
            A[i][j] = (float)(v[7 + i*3 + j] - v[1+i]*v[4+j]*invW);

    float detA = A[0][0]*(A[1][1]*A[2][2]-A[1][2]*A[2][1])
               - A[0][1]*(A[1][0]*A[2][2]-A[1][2]*A[2][0])
               + A[0][2]*(A[1][0]*A[2][1]-A[1][1]*A[2][0]);

    float C[3][3];
    for (int i = 0; i < 3; i++)
        for (int j = 0; j < 3; j++) {
            float s = 0.f;
            for (int k = 0; k < 3; k++) s += A[k][i]*A[k][j];
            C[i][j] = s;
        }
    float V[3][3] = {{1,0,0},{0,1,0},{0,0,1}};
#pragma unroll
    for (int sweep = 0; sweep < 4; sweep++) {
#pragma unroll
        for (int p = 0; p < 3; p++)
#pragma unroll
            for (int q = p+1; q < 3; q++) {
                float apq = C[p][q];
                if (apq == 0.f) continue;
                float theta = __fdividef(C[q][q] - C[p][p], 2.f * apq);
                float tt = (theta >= 0.f ? 1.f : -1.f) *
                           __fdividef(1.f, fabsf(theta) + sqrtf(theta*theta + 1.f));
                float c = rsqrtf(tt*tt + 1.f), s = tt * c;
                for (int k = 0; k < 3; k++) {
                    float a = C[k][p], bb = C[k][q];
                    C[k][p] = c*a - s*bb;  C[k][q] = s*a + c*bb;
                }
                for (int k = 0; k < 3; k++) {
                    float a = C[p][k], bb = C[q][k];
                    C[p][k] = c*a - s*bb;  C[q][k] = s*a + c*bb;
                }
                for (int k = 0; k < 3; k++) {
                    float a = V[k][p], bb = V[k][q];
                    V[k][p] = c*a - s*bb;  V[k][q] = s*a + c*bb;
                }
            }
    }
    float eig[3] = { C[0][0], C[1][1], C[2][2] };
    int idx[3] = {0, 1, 2};
    for (int i = 0; i < 2; i++)
        for (int j = i+1; j < 3; j++)
            if (eig[idx[j]] > eig[idx[i]]) { int tmp = idx[i]; idx[i] = idx[j]; idx[j] = tmp; }

    float emax = fmaxf(eig[idx[0]], 0.f);
    float dinv[3];
    for (int i = 0; i < 3; i++) {
        float e = fmaxf(eig[idx[i]], 0.f);
        dinv[i] = (e > 1e-12f * emax && e > 0.f) ? rsqrtf(e) : 0.f;
    }
    if (detA < 0.f) dinv[2] = -dinv[2];

    float T[3][3];
    for (int i = 0; i < 3; i++)
        for (int j = 0; j < 3; j++) {
            float s = 0.f;
            for (int k = 0; k < 3; k++) s += A[i][k] * V[k][idx[j]];
            T[i][j] = s * dinv[j];
        }
    for (int i = 0; i < 3; i++)
        for (int j = 0; j < 3; j++) {
            float s = 0.f;
            for (int k = 0; k < 3; k++) s += T[i][k] * V[j][idx[k]];
            g_par[b][i*3 + j] = s;
        }
    g_par[b][9]  = mu[0];   g_par[b][10] = mu[1];   g_par[b][11] = mu[2];
    g_par[b][12] = muGT[0]; g_par[b][13] = muGT[1]; g_par[b][14] = muGT[2];
    g_W[b] = W;
}

// ---------------------------------------------------------------------------
// Fallback K1 (general shapes): 18-moment reduction + solve.
// ---------------------------------------------------------------------------
__global__ void __launch_bounds__(256)
reduce_solve_kernel(const float* __restrict__ pred,
                    const float* __restrict__ gt,
                    const float* __restrict__ w,
                    int N, int blocksPerB)
{
    const int b   = blockIdx.x / blocksPerB;
    const int blk = blockIdx.x % blocksPerB;
    const int t   = threadIdx.x;
    const float* pb = pred + (size_t)b * N * 3;
    const float* gb = gt   + (size_t)b * N * 3;
    const float* wb = w    + (size_t)b * N;

    float acc[NMOM];
#pragma unroll
    for (int i = 0; i < NMOM; i++) acc[i] = 0.f;
    for (int n = blk * blockDim.x + t; n < N; n += blocksPerB * blockDim.x) {
        float wn = wb[n];
        float px = pb[3*n], py = pb[3*n+1], pz = pb[3*n+2];
        float gx = gb[3*n], gy = gb[3*n+1], gz = gb[3*n+2];
        float wpx = wn*px, wpy = wn*py, wpz = wn*pz;
        acc[0] += wn;
        acc[1] += wpx;  acc[2] += wpy;  acc[3] += wpz;
        acc[4] += wn*gx; acc[5] += wn*gy; acc[6] += wn*gz;
        acc[7] += wpx*gx; acc[8] += wpx*gy; acc[9] += wpx*gz;
        acc[10] += wpy*gx; acc[11] += wpy*gy; acc[12] += wpy*gz;
        acc[13] += wpz*gx; acc[14] += wpz*gy; acc[15] += wpz*gz;
        acc[16] += wpx*px + wpy*py + wpz*pz;
        acc[17] += wn*(gx*gx + gy*gy + gz*gz);
    }
    const unsigned mask = 0xffffffffu;
#pragma unroll
    for (int i = 0; i < NMOM; i++)
        for (int o = 16; o > 0; o >>= 1)
            acc[i] += __shfl_down_sync(mask, acc[i], o);
    __shared__ float sred[8][NMOM];
    int warp = t >> 5, lane = t & 31;
    if (lane == 0)
#pragma unroll
        for (int i = 0; i < NMOM; i++) sred[warp][i] = acc[i];
    __syncthreads();
    if (t != 0) return;
    double v[NMOM];
#pragma unroll
    for (int i = 0; i < NMOM; i++) {
        float s = 0.f;
        for (int wi = 0; wi < 8; wi++) s += sred[wi][i];
        g_part[b][blk][i] = (double)s;
    }
    __threadfence();
    unsigned old = atomicInc(&g_cnt[b], (unsigned)(blocksPerB - 1));
    if (old != (unsigned)(blocksPerB - 1)) return;
    __threadfence();
    double vv[NMOM];
    for (int i = 0; i < NMOM; i++) {
        double s = 0.0;
        for (int k = 0; k < blocksPerB; k++) s += g_part[b][k][i];
        vv[i] = s;
    }
    kabsch_solve(vv, b);
    g_num1[b] = 0.0;
    if (b == 0) g_bond = 0.0;
    __threadfence();
}

// ---------------------------------------------------------------------------
// Fused kernel: diag blocks [0, B*tilesI), solver blocks [B*tilesI, +B),
// off-diag after. thread t: rows 4*(t&63)+{0..3}, j-eighth (t>>6).
// ---------------------------------------------------------------------------
__global__ void __launch_bounds__(NTHR)
fused_kernel(const float* __restrict__ pred,
             const float* __restrict__ gt,
             const float* __restrict__ w,
             const float* __restrict__ ht,
             float* __restrict__ out,
             int N, int B, int tilesI, int ntri, int precomputed)
{
    const int t  = threadIdx.x;
    const int blk = blockIdx.x;
    const int diagCount = B * tilesI;
    const int nSolver = precomputed ? 0 : B;
    const unsigned mask = 0xffffffffu;

    // ================= solver blocks =================
    if (!precomputed && blk >= diagCount && blk < diagCount + B) {
        if (t < 32) {
            const int b = blk - diagCount;
            __shared__ double svv[NMOM];
            if (t == 0) {
                unsigned c;
                do {
                    asm volatile("ld.acquire.gpu.u32 %0, [%1];"
                                 : "=r"(c) : "l"(&g_cnt[b]) : "memory");
                } while (c < (unsigned)tilesI);
            }
            __syncwarp(mask);
            if (t < NMOM) {
                double s = 0.0;
                for (int k = 0; k < tilesI; k++) s += g_part[b][k][t];
                svv[t] = s;
            }
            __syncwarp(mask);
            if (t == 0) {
                kabsch_solve(svv, b);
                g_cnt[b] = 0;                 // reset for next replay
                __threadfence();
                atomicExch(&g_ready[b], 1);
                // participate in global completion
                unsigned old = atomicInc(&g_done, (unsigned)(gridDim.x - 1));
                if (old == (unsigned)(gridDim.x - 1)) {
                    __threadfence();
                    float sw = 0.f, sw2 = 0.f, sn = 0.f, scl = 0.f;
                    for (int bb = 0; bb < B; bb++) {
                        float W = (float)g_W[bb];
                        sw += W; sw2 += W * W;
                        sn += (float)g_num1[bb]; scl += (float)g_closed[bb];
                    }
                    float bond = (float)g_bond;
                    float loss = __fdividef(sn, sw)
                               + __fdividef(scl - 2.f * bond, sw2);
                    for (int bb = 0; bb < B; bb++) {
                        float h = __ldg(&ht[bb]);
                        float d = (h + 16.f);
                        out[bb] = (h*h + 256.f) * __fdividef(loss, d*d);
                    }
                    g_bond = 0.0;
                    for (int bb = 0; bb < B; bb++) { g_num1[bb] = 0.0; g_ready[bb] = 0; }
                    __threadfence();
                }
            }
        }
        return;
    }

    // ================= tile blocks =================
    const int rp = t & 63;
    const int jq = t >> 6;
    const int nOff = ntri - tilesI;

    int b, ti, tj;
    bool diag;
    if (blk < diagCount) {
        diag = true;
        b = blk / tilesI;
        ti = tj = blk % tilesI;
    } else {
        diag = false;
        int rem = blk - diagCount - nSolver;
        b = rem / nOff;
        int r2 = rem % nOff;
        ti = 0;
        int rowlen = tilesI - 1;
        while (r2 >= rowlen) { r2 -= rowlen; ti++; rowlen--; }
        tj = ti + 1 + r2;
    }

    const float* pb = pred + (size_t)b * N * 3;
    const float* gb = gt   + (size_t)b * N * 3;
    const float* wb = w    + (size_t)b * N;

    __shared__ float rawPI[TILE*3], rawGI[TILE*3], rawWI[TILE];
    __shared__ float rawPJ[TILE*3], rawGJ[TILE*3], rawWJ[TILE];
    __shared__ float4 sA[TILE];   // (pjx, gjx, pjy, gjy)
    __shared__ float4 sZ[TILE];   // (pjz, gjz, pn2j, gn2j)
    __shared__ float  sW[TILE];
    __shared__ float  sredM[2][NMOM];
    __shared__ float  sredp[NTHR/32];
    __shared__ float  sreda[2];

    // ---- stage tiles with coalesced LDG ----
    {
        int baseI3 = ti * TILE * 3, baseJ3 = tj * TILE * 3;
        int baseI = ti * TILE, baseJ = tj * TILE;
        int n3 = 3 * N;
#pragma unroll
        for (int idx = t; idx < TILE*3; idx += NTHR) {
            int gi = baseI3 + idx;
            float pv = 0.f, gv = 0.f;
            if (gi < n3) { pv = pb[gi]; gv = gb[gi]; }
            rawPI[idx] = pv; rawGI[idx] = gv;
        }
        if (t < TILE) {
            int gi = baseI + t;
            rawWI[t] = (gi < N) ? wb[gi] : 0.f;
        }
        if (!diag) {
#pragma unroll
            for (int idx = t; idx < TILE*3; idx += NTHR) {
                int gi = baseJ3 + idx;
                float pv = 0.f, gv = 0.f;
                if (gi < n3) { pv = pb[gi]; gv = gb[gi]; }
                rawPJ[idx] = pv; rawGJ[idx] = gv;
            }
            if (t < TILE) {
                int gi = baseJ + t;
                rawWJ[t] = (gi < N) ? wb[gi] : 0.f;
            }
        }
    }
    __syncthreads();

    const float* RPJ = diag ? rawPI : rawPJ;
    const float* RGJ = diag ? rawGI : rawGJ;
    const float* RWJ = diag ? rawWI : rawWJ;

    // ---- format j tile from smem (threads 0..255) ----
    if (t < TILE) {
        float px = RPJ[3*t], py = RPJ[3*t+1], pz = RPJ[3*t+2];
        float gx = RGJ[3*t], gy = RGJ[3*t+1], gz = RGJ[3*t+2];
        sA[t] = make_float4(px, gx, py, gy);
        sZ[t] = make_float4(pz, gz, px*px+py*py+pz*pz, gx*gx+gy*gy+gz*gz);
        sW[t] = RWJ[t];
    }

    // ---- load four i-rows into registers from smem ----
    float pxr[4], pyr[4], pzr[4], gxr[4], gyr[4], gzr[4], wr[4];
#pragma unroll
    for (int r = 0; r < 4; r++) {
        int li = 4*rp + r;
        pxr[r] = rawPI[3*li];   pyr[r] = rawPI[3*li+1]; pzr[r] = rawPI[3*li+2];
        gxr[r] = rawGI[3*li];   gyr[r] = rawGI[3*li+1]; gzr[r] = rawGI[3*li+2];
        wr[r]  = rawWI[li];
    }

    unsigned long long ax[4], ay[4], az[4], bs[4];
#pragma unroll
    for (int r = 0; r < 4; r++) {
        PACK_F32X2(ax[r], -2.f*pxr[r], -2.f*gxr[r]);
        PACK_F32X2(ay[r], -2.f*pyr[r], -2.f*gyr[r]);
        PACK_F32X2(az[r], -2.f*pzr[r], -2.f*gzr[r]);
        PACK_F32X2(bs[r], pxr[r]*pxr[r]+pyr[r]*pyr[r]+pzr[r]*pzr[r],
                          gxr[r]*gxr[r]+gyr[r]*gyr[r]+gzr[r]*gzr[r]);
    }

    int warp = t >> 5, lane = t & 31;

    // ---- stats partial (diag blocks; threads t<64 own the 256 rows) ----
    if (diag && !precomputed) {
        if (t < 64) {
            float acc[NMOM];
#pragma unroll
            for (int i = 0; i < NMOM; i++) acc[i] = 0.f;
#pragma unroll
            for (int r = 0; r < 4; r++) {
                float wn = wr[r];
                float px = pxr[r], py = pyr[r], pz = pzr[r];
                float gx = gxr[r], gy = gyr[r], gz = gzr[r];
                float wpx = wn*px, wpy = wn*py, wpz = wn*pz;
                acc[0] += wn;
                acc[1] += wpx;  acc[2] += wpy;  acc[3] += wpz;
                acc[4] += wn*gx; acc[5] += wn*gy; acc[6] += wn*gz;
                acc[7] += wpx*gx; acc[8] += wpx*gy; acc[9] += wpx*gz;
                acc[10] += wpy*gx; acc[11] += wpy*gy; acc[12] += wpy*gz;
                acc[13] += wpz*gx; acc[14] += wpz*gy; acc[15] += wpz*gz;
                acc[16] += wpx*px + wpy*py + wpz*pz;
                acc[17] += wn*(gx*gx + gy*gy + gz*gz);
            }
#pragma unroll
            for (int i = 0; i < NMOM; i++)
                for (int o = 16; o > 0; o >>= 1)
                    acc[i] += __shfl_down_sync(mask, acc[i], o);
            if (lane == 0)
#pragma unroll
                for (int i = 0; i < NMOM; i++) sredM[warp][i] = acc[i];
        }
        __syncthreads();   // sredM + sA/sZ/sW visible
        if (t == 0) {
#pragma unroll
            for (int i = 0; i < NMOM; i++)
                g_part[b][ti][i] = (double)(sredM[0][i] + sredM[1][i]);
            __threadfence();
            atomicAdd(&g_cnt[b], 1u);   // solver block gathers + solves
        }
    } else {
        __syncthreads();   // sA/sZ/sW visible
    }

    // ---- cross-term loop: acc_r += wj * sqrt(|dp2*dg2|), 4 rows x 32 j ----
    float accr[4] = {0.f, 0.f, 0.f, 0.f};
    const int kbase = jq * 32;
#pragma unroll 4
    for (int kk = 0; kk < 32; kk++) {
        int k = kbase + kk;
        ulonglong2 A = *reinterpret_cast<const ulonglong2*>(&sA[k]);
        ulonglong2 Z = *reinterpret_cast<const ulonglong2*>(&sZ[k]);
        float wj = sW[k];
#pragma unroll
        for (int r = 0; r < 4; r++) {
            unsigned long long c;
            FMA_F32X2(c, az[r], Z.x, Z.y);   // -2z*zj + (pn2j,gn2j)
            FMA_F32X2(c, ay[r], A.y, c);
            FMA_F32X2(c, ax[r], A.x, c);
            ADD_F32X2(c, c, bs[r]);          // -> (dp2, dg2)
            float dp2, dg2;
            UNPACK_F32X2(dp2, dg2, c);
            float s = fsqrt_approx(fabsf(dp2 * dg2));  // |.| folds into MUFU
            accr[r] = fmaf(wj, s, accr[r]);
        }
    }

    float tot = accr[0]*wr[0] + accr[1]*wr[1] + accr[2]*wr[2] + accr[3]*wr[3];
    if (!diag) tot *= 2.f;           // symmetry
    for (int o = 16; o > 0; o >>= 1)
        tot += __shfl_down_sync(mask, tot, o);
    if (lane == 0) sredp[warp] = tot;

    // ---- fused alignment loss (diag blocks; flag set by solver already) ----
    if (diag) {
        if (!precomputed && t == 0) {
            int r;
            do {
                asm volatile("ld.acquire.gpu.b32 %0, [%1];"
                             : "=r"(r) : "l"(&g_ready[b]) : "memory");
            } while (r == 0);
        }
        __syncthreads();
        if (t < 64) {
            float R00 = g_par[b][0], R01 = g_par[b][1], R02 = g_par[b][2];
            float R10 = g_par[b][3], R11 = g_par[b][4], R12 = g_par[b][5];
            float R20 = g_par[b][6], R21 = g_par[b][7], R22 = g_par[b][8];
            float mux = g_par[b][9],  muy = g_par[b][10], muz = g_par[b][11];
            float mgx = g_par[b][12], mgy = g_par[b][13], mgz = g_par[b][14];

            float alf = 0.f;
#pragma unroll
            for (int r = 0; r < 4; r++) {
                float gx = gxr[r] - mux, gy = gyr[r] - muy, gz = gzr[r] - muz;
                float axv = R00*gx + R01*gy + R02*gz + mgx;
                float ayv = R10*gx + R11*gy + R12*gz + mgy;
                float azv = R20*gx + R21*gy + R22*gz + mgz;
                float dx = pxr[r] - axv, dy = pyr[r] - ayv, dz = pzr[r] - azv;
                alf += wr[r] * fsqrt_approx(dx*dx + dy*dy + dz*dz);
            }
            for (int o = 16; o > 0; o >>= 1)
                alf += __shfl_down_sync(mask, alf, o);
            if (lane == 0) sreda[warp] = alf;
        }
    }
    __syncthreads();

    // ---- block totals + global completion ----
    if (t == 0) {
        float s = 0.f;
        for (int wi = 0; wi < NTHR/32; wi++) s += sredp[wi];
        atomicAdd(&g_bond, (double)s);
        if (diag)
            atomicAdd(&g_num1[b], (double)(sreda[0] + sreda[1]));
        __threadfence();
        unsigned old = atomicInc(&g_done, (unsigned)(gridDim.x - 1));
        if (old == (unsigned)(gridDim.x - 1)) {
            __threadfence();
            float sw = 0.f, sw2 = 0.f, sn = 0.f, scl = 0.f;
            for (int bb = 0; bb < B; bb++) {
                float W = (float)g_W[bb];
                sw += W; sw2 += W * W;
                sn += (float)g_num1[bb]; scl += (float)g_closed[bb];
            }
            float bond = (float)g_bond;
            float loss = __fdividef(sn, sw)
                       + __fdividef(scl - 2.f * bond, sw2);
            for (int bb = 0; bb < B; bb++) {
                float h = __ldg(&ht[bb]);
                float d = (h + 16.f);
                out[bb] = (h*h + 256.f) * __fdividef(loss, d*d);
            }
            g_bond = 0.0;
            for (int bb = 0; bb < B; bb++) { g_num1[bb] = 0.0; g_ready[bb] = 0; }
            __threadfence();
        }
    }
}

extern "C" void kernel_launch(void* const* d_in, const int* in_sizes, int n_in,
                              void* d_out, int out_size)
{
    const float* pred = (const float*)d_in[0];
    const float* gt   = (const float*)d_in[1];
    const float* ht   = (const float*)d_in[2];
    const float* w    = (const float*)d_in[3];
    int B = in_sizes[2];
    int N = in_sizes[3] / B;

    int tilesI = (N + TILE - 1) / TILE;
    int ntri = tilesI * (tilesI + 1) / 2;

    if (B * ntri + B <= 148 && tilesI <= MAXBLK && B <= MAXB) {
        // fused with dedicated solver blocks; all co-resident in one wave
        fused_kernel<<<B * ntri + B, NTHR>>>(pred, gt, w, ht, (float*)d_out,
                                             N, B, tilesI, ntri, 0);
    } else {
        int blocksPerB = (N + 255) / 256;
        if (blocksPerB > MAXBLK) blocksPerB = MAXBLK;
        reduce_solve_kernel<<<B * blocksPerB, 256>>>(pred, gt, w, N, blocksPerB);
        fused_kernel<<<B * ntri, NTHR>>>(pred, gt, w, ht, (float*)d_out,
                                         N, B, tilesI, ntri, 1);
    }
}

// round 12
// speedup vs baseline: 1.8512x; 1.0094x over previous
#include <cuda_runtime.h>
#include <math.h>

// ---------------------------------------------------------------------------
// DiffusionLoss fused single-kernel, 1024 threads/block (8 warps/SMSP).
// grid = B*ntri + B = 148 blocks (exactly one wave, all co-resident).
//   - diag blocks: stage tile, stats partial -> g_cnt, bond loop, align loss.
//   - B solver blocks: spin on g_cnt, gather, 3x3 Kabsch, release g_ready
//     (concurrent with bond compute).
//   - off-diag blocks: stage 2 tiles, bond loop only (x2 symmetry).
// Bond: sum_ij wiwj (dp-dg)^2 = [closed form O(N)] - 2*sum_ij wiwj dp*dg
//   -> O(N^2) loop computes only wi wj sqrt(|dp2*dg2|) (packed f32x2, 1 MUFU).
// thread t: rows 2*(t&127)+{0,1} of tile ti, j-eighth (t>>7) of tile tj.
// ---------------------------------------------------------------------------

#define MAXB 16
#define MAXBLK 64
#define TILE 256
#define NTHR 1024
#define NMOM 18

__device__ double   g_part[MAXB][MAXBLK][NMOM];
__device__ unsigned g_cnt[MAXB];       // stats arrivals (reset by solver)
__device__ int      g_ready[MAXB];     // solve-done flag (reset by combiner)
__device__ float    g_par[MAXB][15];   // R[9], mu[3], muGT[3]
__device__ double   g_W[MAXB];
__device__ double   g_closed[MAXB];
__device__ double   g_num1[MAXB];
__device__ double   g_bond;
__device__ unsigned g_done;

__device__ __forceinline__ float fsqrt_approx(float x) {
    float r;
    asm("sqrt.approx.f32 %0, %1;" : "=f"(r) : "f"(x));
    return r;
}

#define PACK_F32X2(out, lo, hi) \
    asm("mov.b64 %0, {%1, %2};" : "=l"(out) : "f"(lo), "f"(hi))
#define UNPACK_F32X2(lo, hi, in) \
    asm("mov.b64 {%0, %1}, %2;" : "=f"(lo), "=f"(hi) : "l"(in))
#define ADD_F32X2(out, a, b) \
    asm("add.rn.f32x2 %0, %1, %2;" : "=l"(out) : "l"(a), "l"(b))
#define FMA_F32X2(d, a, b, c) \
    asm("fma.rn.f32x2 %0, %1, %2, %3;" : "=l"(d) : "l"(a), "l"(b), "l"(c))

// ---------------------------------------------------------------------------
// 3x3 Kabsch solve from moments v[18]; also stores the closed-form term.
// ---------------------------------------------------------------------------
__device__ void kabsch_solve(const double* v, int b)
{
    double W = v[0];
    double invW = 1.0 / W;
    double spw2 = v[1]*v[1] + v[2]*v[2] + v[3]*v[3];
    double sgw2 = v[4]*v[4] + v[5]*v[5] + v[6]*v[6];
    g_closed[b] = 2.0*(W*v[16] - spw2) + 2.0*(W*v[17] - sgw2);

    // mu = GT weighted mean, muGT = pred mean (arg-swap in reference)
    float muGT[3] = { (float)(v[1]*invW), (float)(v[2]*invW), (float)(v[3]*invW) };
    float mu[3]   = { (float)(v[4]*invW), (float)(v[5]*invW), (float)(v[6]*invW) };

    float A[3][3];
    for (int i = 0; i < 3; i++)
        for (int j = 0; j < 3; j++)
            A[i][j] = (float)(v[7 + i*3 + j] - v[1+i]*v[4+j]*invW);

    float detA = A[0][0]*(A[1][1]*A[2][2]-A[1][2]*A[2][1])
               - A[0][1]*(A[1][0]*A[2][2]-A[1][2]*A[2][0])
               + A[0][2]*(A[1][0]*A[2][1]-A[1][1]*A[2][0]);

    float C[3][3];
    for (int i = 0; i < 3; i++)
        for (int j = 0; j < 3; j++) {
            float s = 0.f;
            for (int k = 0; k < 3; k++) s += A[k][i]*A[k][j];
            C[i][j] = s;
        }
    float V[3][3] = {{1,0,0},{0,1,0},{0,0,1}};
#pragma unroll
    for (int sweep = 0; sweep < 4; sweep++) {
#pragma unroll
        for (int p = 0; p < 3; p++)
#pragma unroll
            for (int q = p+1; q < 3; q++) {
                float apq = C[p][q];
                if (apq == 0.f) continue;
                float theta = __fdividef(C[q][q] - C[p][p], 2.f * apq);
                float tt = (theta >= 0.f ? 1.f : -1.f) *
                           __fdividef(1.f, fabsf(theta) + sqrtf(theta*theta + 1.f));
                float c = rsqrtf(tt*tt + 1.f), s = tt * c;
                for (int k = 0; k < 3; k++) {
                    float a = C[k][p], bb = C[k][q];
                    C[k][p] = c*a - s*bb;  C[k][q] = s*a + c*bb;
                }
                for (int k = 0; k < 3; k++) {
                    float a = C[p][k], bb = C[q][k];
                    C[p][k] = c*a - s*bb;  C[q][k] = s*a + c*bb;
                }
                for (int k = 0; k < 3; k++) {
                    float a = V[k][p], bb = V[k][q];
                    V[k][p] = c*a - s*bb;  V[k][q] = s*a + c*bb;
                }
            }
    }
    float eig[3] = { C[0][0], C[1][1], C[2][2] };
    int idx[3] = {0, 1, 2};
    for (int i = 0; i < 2; i++)
        for (int j = i+1; j < 3; j++)
            if (eig[idx[j]] > eig[idx[i]]) { int tmp = idx[i]; idx[i] = idx[j]; idx[j] = tmp; }

    float emax = fmaxf(eig[idx[0]], 0.f);
    float dinv[3];
    for (int i = 0; i < 3; i++) {
        float e = fmaxf(eig[idx[i]], 0.f);
        dinv[i] = (e > 1e-12f * emax && e > 0.f) ? rsqrtf(e) : 0.f;
    }
    if (detA < 0.f) dinv[2] = -dinv[2];

    float T[3][3];
    for (int i = 0; i < 3; i++)
        for (int j = 0; j < 3; j++) {
            float s = 0.f;
            for (int k = 0; k < 3; k++) s += A[i][k] * V[k][idx[j]];
            T[i][j] = s * dinv[j];
        }
    for (int i = 0; i < 3; i++)
        for (int j = 0; j < 3; j++) {
            float s = 0.f;
            for (int k = 0; k < 3; k++) s += T[i][k] * V[j][idx[k]];
            g_par[b][i*3 + j] = s;
        }
    g_par[b][9]  = mu[0];   g_par[b][10] = mu[1];   g_par[b][11] = mu[2];
    g_par[b][12] = muGT[0]; g_par[b][13] = muGT[1]; g_par[b][14] = muGT[2];
    g_W[b] = W;
}

// ---------------------------------------------------------------------------
// Fallback K1 (general shapes): 18-moment reduction + solve.
// ---------------------------------------------------------------------------
__global__ void __launch_bounds__(256)
reduce_solve_kernel(const float* __restrict__ pred,
                    const float* __restrict__ gt,
                    const float* __restrict__ w,
                    int N, int blocksPerB)
{
    const int b   = blockIdx.x / blocksPerB;
    const int blk = blockIdx.x % blocksPerB;
    const int t   = threadIdx.x;
    const float* pb = pred + (size_t)b * N * 3;
    const float* gb = gt   + (size_t)b * N * 3;
    const float* wb = w    + (size_t)b * N;

    float acc[NMOM];
#pragma unroll
    for (int i = 0; i < NMOM; i++) acc[i] = 0.f;
    for (int n = blk * blockDim.x + t; n < N; n += blocksPerB * blockDim.x) {
        float wn = wb[n];
        float px = pb[3*n], py = pb[3*n+1], pz = pb[3*n+2];
        float gx = gb[3*n], gy = gb[3*n+1], gz = gb[3*n+2];
        float wpx = wn*px, wpy = wn*py, wpz = wn*pz;
        acc[0] += wn;
        acc[1] += wpx;  acc[2] += wpy;  acc[3] += wpz;
        acc[4] += wn*gx; acc[5] += wn*gy; acc[6] += wn*gz;
        acc[7] += wpx*gx; acc[8] += wpx*gy; acc[9] += wpx*gz;
        acc[10] += wpy*gx; acc[11] += wpy*gy; acc[12] += wpy*gz;
        acc[13] += wpz*gx; acc[14] += wpz*gy; acc[15] += wpz*gz;
        acc[16] += wpx*px + wpy*py + wpz*pz;
        acc[17] += wn*(gx*gx + gy*gy + gz*gz);
    }
    const unsigned mask = 0xffffffffu;
#pragma unroll
    for (int i = 0; i < NMOM; i++)
        for (int o = 16; o > 0; o >>= 1)
            acc[i] += __shfl_down_sync(mask, acc[i], o);
    __shared__ float sred[8][NMOM];
    int warp = t >> 5, lane = t & 31;
    if (lane == 0)
#pragma unroll
        for (int i = 0; i < NMOM; i++) sred[warp][i] = acc[i];
    __syncthreads();
    if (t != 0) return;
    double v[NMOM];
#pragma unroll
    for (int i = 0; i < NMOM; i++) {
        float s = 0.f;
        for (int wi = 0; wi < 8; wi++) s += sred[wi][i];
        g_part[b][blk][i] = (double)s;
    }
    __threadfence();
    unsigned old = atomicInc(&g_cnt[b], (unsigned)(blocksPerB - 1));
    if (old != (unsigned)(blocksPerB - 1)) return;
    __threadfence();
    double vv[NMOM];
    for (int i = 0; i < NMOM; i++) {
        double s = 0.0;
        for (int k = 0; k < blocksPerB; k++) s += g_part[b][k][i];
        vv[i] = s;
    }
    kabsch_solve(vv, b);
    g_num1[b] = 0.0;
    if (b == 0) g_bond = 0.0;
    __threadfence();
}

// ---------------------------------------------------------------------------
// Fused kernel (1024 threads).
// ---------------------------------------------------------------------------
__global__ void __launch_bounds__(NTHR)
fused_kernel(const float* __restrict__ pred,
             const float* __restrict__ gt,
             const float* __restrict__ w,
             const float* __restrict__ ht,
             float* __restrict__ out,
             int N, int B, int tilesI, int ntri, int precomputed)
{
    const int t  = threadIdx.x;
    const int blk = blockIdx.x;
    const int diagCount = B * tilesI;
    const int nSolver = precomputed ? 0 : B;
    const unsigned mask = 0xffffffffu;

    // ================= solver blocks =================
    if (!precomputed && blk >= diagCount && blk < diagCount + B) {
        if (t < 32) {
            const int b = blk - diagCount;
            __shared__ double svv[NMOM];
            if (t == 0) {
                unsigned c;
                do {
                    asm volatile("ld.acquire.gpu.u32 %0, [%1];"
                                 : "=r"(c) : "l"(&g_cnt[b]) : "memory");
                } while (c < (unsigned)tilesI);
            }
            __syncwarp(mask);
            if (t < NMOM) {
                double s = 0.0;
                for (int k = 0; k < tilesI; k++) s += g_part[b][k][t];
                svv[t] = s;
            }
            __syncwarp(mask);
            if (t == 0) {
                kabsch_solve(svv, b);
                g_cnt[b] = 0;                 // reset for next replay
                __threadfence();
                atomicExch(&g_ready[b], 1);
                unsigned old = atomicInc(&g_done, (unsigned)(gridDim.x - 1));
                if (old == (unsigned)(gridDim.x - 1)) {
                    __threadfence();
                    float sw = 0.f, sw2 = 0.f, sn = 0.f, scl = 0.f;
                    for (int bb = 0; bb < B; bb++) {
                        float W = (float)g_W[bb];
                        sw += W; sw2 += W * W;
                        sn += (float)g_num1[bb]; scl += (float)g_closed[bb];
                    }
                    float bond = (float)g_bond;
                    float loss = __fdividef(sn, sw)
                               + __fdividef(scl - 2.f * bond, sw2);
                    for (int bb = 0; bb < B; bb++) {
                        float h = __ldg(&ht[bb]);
                        float d = (h + 16.f);
                        out[bb] = (h*h + 256.f) * __fdividef(loss, d*d);
                    }
                    g_bond = 0.0;
                    for (int bb = 0; bb < B; bb++) { g_num1[bb] = 0.0; g_ready[bb] = 0; }
                    __threadfence();
                }
            }
        }
        return;
    }

    // ================= tile blocks =================
    const int rp = t & 127;          // row-pair index (128 pairs = 256 rows)
    const int jq = t >> 7;           // j eighth 0..7 (32 j's each)
    const int nOff = ntri - tilesI;

    int b, ti, tj;
    bool diag;
    if (blk < diagCount) {
        diag = true;
        b = blk / tilesI;
        ti = tj = blk % tilesI;
    } else {
        diag = false;
        int rem = blk - diagCount - nSolver;
        b = rem / nOff;
        int r2 = rem % nOff;
        ti = 0;
        int rowlen = tilesI - 1;
        while (r2 >= rowlen) { r2 -= rowlen; ti++; rowlen--; }
        tj = ti + 1 + r2;
    }

    const float* pb = pred + (size_t)b * N * 3;
    const float* gb = gt   + (size_t)b * N * 3;
    const float* wb = w    + (size_t)b * N;

    __shared__ float rawPI[TILE*3], rawGI[TILE*3], rawWI[TILE];
    __shared__ float rawPJ[TILE*3], rawGJ[TILE*3], rawWJ[TILE];
    __shared__ float4 sA[TILE];   // (pjx, gjx, pjy, gjy)
    __shared__ float4 sZ[TILE];   // (pjz, gjz, pn2j, gn2j)
    __shared__ float  sW[TILE];
    __shared__ float  sredM[4][NMOM];
    __shared__ float  sredp[NTHR/32];
    __shared__ float  sreda[4];

    // ---- stage tiles with coalesced LDG ----
    {
        int baseI3 = ti * TILE * 3, baseJ3 = tj * TILE * 3;
        int baseI = ti * TILE, baseJ = tj * TILE;
        int n3 = 3 * N;
        if (t < TILE*3) {
            int gi = baseI3 + t;
            float pv = 0.f, gv = 0.f;
            if (gi < n3) { pv = pb[gi]; gv = gb[gi]; }
            rawPI[t] = pv; rawGI[t] = gv;
        }
        if (t < TILE) {
            int gi = baseI + t;
            rawWI[t] = (gi < N) ? wb[gi] : 0.f;
        }
        if (!diag) {
            if (t < TILE*3) {
                int gi = baseJ3 + t;
                float pv = 0.f, gv = 0.f;
                if (gi < n3) { pv = pb[gi]; gv = gb[gi]; }
                rawPJ[t] = pv; rawGJ[t] = gv;
            }
            if (t < TILE) {
                int gi = baseJ + t;
                rawWJ[t] = (gi < N) ? wb[gi] : 0.f;
            }
        }
    }
    __syncthreads();

    const float* RPJ = diag ? rawPI : rawPJ;
    const float* RGJ = diag ? rawGI : rawGJ;
    const float* RWJ = diag ? rawWI : rawWJ;

    // ---- format j tile from smem (threads 0..255) ----
    if (t < TILE) {
        float px = RPJ[3*t], py = RPJ[3*t+1], pz = RPJ[3*t+2];
        float gx = RGJ[3*t], gy = RGJ[3*t+1], gz = RGJ[3*t+2];
        sA[t] = make_float4(px, gx, py, gy);
        sZ[t] = make_float4(pz, gz, px*px+py*py+pz*pz, gx*gx+gy*gy+gz*gz);
        sW[t] = RWJ[t];
    }

    // ---- load two i-rows into registers from smem ----
    float pxr[2], pyr[2], pzr[2], gxr[2], gyr[2], gzr[2], wr[2];
#pragma unroll
    for (int r = 0; r < 2; r++) {
        int li = 2*rp + r;
        pxr[r] = rawPI[3*li];   pyr[r] = rawPI[3*li+1]; pzr[r] = rawPI[3*li+2];
        gxr[r] = rawGI[3*li];   gyr[r] = rawGI[3*li+1]; gzr[r] = rawGI[3*li+2];
        wr[r]  = rawWI[li];
    }

    unsigned long long ax[2], ay[2], az[2], bs[2];
#pragma unroll
    for (int r = 0; r < 2; r++) {
        PACK_F32X2(ax[r], -2.f*pxr[r], -2.f*gxr[r]);
        PACK_F32X2(ay[r], -2.f*pyr[r], -2.f*gyr[r]);
        PACK_F32X2(az[r], -2.f*pzr[r], -2.f*gzr[r]);
        PACK_F32X2(bs[r], pxr[r]*pxr[r]+pyr[r]*pyr[r]+pzr[r]*pzr[r],
                          gxr[r]*gxr[r]+gyr[r]*gyr[r]+gzr[r]*gzr[r]);
    }

    int warp = t >> 5, lane = t & 31;

    // ---- stats partial (diag blocks; threads t<128 own the 256 rows) ----
    if (diag && !precomputed) {
        if (t < 128) {
            float acc[NMOM];
#pragma unroll
            for (int i = 0; i < NMOM; i++) acc[i] = 0.f;
#pragma unroll
            for (int r = 0; r < 2; r++) {
                float wn = wr[r];
                float px = pxr[r], py = pyr[r], pz = pzr[r];
                float gx = gxr[r], gy = gyr[r], gz = gzr[r];
                float wpx = wn*px, wpy = wn*py, wpz = wn*pz;
                acc[0] += wn;
                acc[1] += wpx;  acc[2] += wpy;  acc[3] += wpz;
                acc[4] += wn*gx; acc[5] += wn*gy; acc[6] += wn*gz;
                acc[7] += wpx*gx; acc[8] += wpx*gy; acc[9] += wpx*gz;
                acc[10] += wpy*gx; acc[11] += wpy*gy; acc[12] += wpy*gz;
                acc[13] += wpz*gx; acc[14] += wpz*gy; acc[15] += wpz*gz;
                acc[16] += wpx*px + wpy*py + wpz*pz;
                acc[17] += wn*(gx*gx + gy*gy + gz*gz);
            }
#pragma unroll
            for (int i = 0; i < NMOM; i++)
                for (int o = 16; o > 0; o >>= 1)
                    acc[i] += __shfl_down_sync(mask, acc[i], o);
            if (lane == 0)
#pragma unroll
                for (int i = 0; i < NMOM; i++) sredM[warp][i] = acc[i];
        }
        __syncthreads();   // sredM + sA/sZ/sW visible
        if (t == 0) {
#pragma unroll
            for (int i = 0; i < NMOM; i++)
                g_part[b][ti][i] = (double)(sredM[0][i] + sredM[1][i]
                                          + sredM[2][i] + sredM[3][i]);
            __threadfence();
            atomicAdd(&g_cnt[b], 1u);   // solver block gathers + solves
        }
    } else {
        __syncthreads();   // sA/sZ/sW visible
    }

    // ---- cross-term loop: acc_r += wj * sqrt(|dp2*dg2|), 2 rows x 32 j ----
    float accr[2] = {0.f, 0.f};
    const int kbase = jq * 32;
#pragma unroll 4
    for (int kk = 0; kk < 32; kk++) {
        int k = kbase + kk;
        ulonglong2 A = *reinterpret_cast<const ulonglong2*>(&sA[k]);
        ulonglong2 Z = *reinterpret_cast<const ulonglong2*>(&sZ[k]);
        float wj = sW[k];
#pragma unroll
        for (int r = 0; r < 2; r++) {
            unsigned long long c;
            FMA_F32X2(c, az[r], Z.x, Z.y);   // -2z*zj + (pn2j,gn2j)
            FMA_F32X2(c, ay[r], A.y, c);
            FMA_F32X2(c, ax[r], A.x, c);
            ADD_F32X2(c, c, bs[r]);          // -> (dp2, dg2)
            float dp2, dg2;
            UNPACK_F32X2(dp2, dg2, c);
            float s = fsqrt_approx(fabsf(dp2 * dg2));  // |.| folds into MUFU
            accr[r] = fmaf(wj, s, accr[r]);
        }
    }

    float tot = accr[0]*wr[0] + accr[1]*wr[1];
    if (!diag) tot *= 2.f;           // symmetry
    for (int o = 16; o > 0; o >>= 1)
        tot += __shfl_down_sync(mask, tot, o);
    if (lane == 0) sredp[warp] = tot;

    // ---- fused alignment loss (diag blocks; flag set by solver already) ----
    if (diag) {
        if (!precomputed && t == 0) {
            int r;
            do {
                asm volatile("ld.acquire.gpu.b32 %0, [%1];"
                             : "=r"(r) : "l"(&g_ready[b]) : "memory");
            } while (r == 0);
        }
        __syncthreads();
        if (t < 128) {
            float R00 = g_par[b][0], R01 = g_par[b][1], R02 = g_par[b][2];
            float R10 = g_par[b][3], R11 = g_par[b][4], R12 = g_par[b][5];
            float R20 = g_par[b][6], R21 = g_par[b][7], R22 = g_par[b][8];
            float mux = g_par[b][9],  muy = g_par[b][10], muz = g_par[b][11];
            float mgx = g_par[b][12], mgy = g_par[b][13], mgz = g_par[b][14];

            float alf = 0.f;
#pragma unroll
            for (int r = 0; r < 2; r++) {
                float gx = gxr[r] - mux, gy = gyr[r] - muy, gz = gzr[r] - muz;
                float axv = R00*gx + R01*gy + R02*gz + mgx;
                float ayv = R10*gx + R11*gy + R12*gz + mgy;
                float azv = R20*gx + R21*gy + R22*gz + mgz;
                float dx = pxr[r] - axv, dy = pyr[r] - ayv, dz = pzr[r] - azv;
                alf += wr[r] * fsqrt_approx(dx*dx + dy*dy + dz*dz);
            }
            for (int o = 16; o > 0; o >>= 1)
                alf += __shfl_down_sync(mask, alf, o);
            if (lane == 0) sreda[warp] = alf;
        }
    }
    __syncthreads();

    // ---- block totals + global completion ----
    if (t == 0) {
        float s = 0.f;
        for (int wi = 0; wi < NTHR/32; wi++) s += sredp[wi];
        atomicAdd(&g_bond, (double)s);
        if (diag)
            atomicAdd(&g_num1[b],
                      (double)(sreda[0] + sreda[1] + sreda[2] + sreda[3]));
        __threadfence();
        unsigned old = atomicInc(&g_done, (unsigned)(gridDim.x - 1));
        if (old == (unsigned)(gridDim.x - 1)) {
            __threadfence();
            float sw = 0.f, sw2 = 0.f, sn = 0.f, scl = 0.f;
            for (int bb = 0; bb < B; bb++) {
                float W = (float)g_W[bb];
                sw += W; sw2 += W * W;
                sn += (float)g_num1[bb]; scl += (float)g_closed[bb];
            }
            float bond = (float)g_bond;
            float loss = __fdividef(sn, sw)
                       + __fdividef(scl - 2.f * bond, sw2);
            for (int bb = 0; bb < B; bb++) {
                float h = __ldg(&ht[bb]);
                float d = (h + 16.f);
                out[bb] = (h*h + 256.f) * __fdividef(loss, d*d);
            }
            g_bond = 0.0;
            for (int bb = 0; bb < B; bb++) { g_num1[bb] = 0.0; g_ready[bb] = 0; }
            __threadfence();
        }
    }
}

extern "C" void kernel_launch(void* const* d_in, const int* in_sizes, int n_in,
                              void* d_out, int out_size)
{
    const float* pred = (const float*)d_in[0];
    const float* gt   = (const float*)d_in[1];
    const float* ht   = (const float*)d_in[2];
    const float* w    = (const float*)d_in[3];
    int B = in_sizes[2];
    int N = in_sizes[3] / B;

    int tilesI = (N + TILE - 1) / TILE;
    int ntri = tilesI * (tilesI + 1) / 2;

    if (B * ntri + B <= 148 && tilesI <= MAXBLK && B <= MAXB) {
        fused_kernel<<<B * ntri + B, NTHR>>>(pred, gt, w, ht, (float*)d_out,
                                             N, B, tilesI, ntri, 0);
    } else {
        int blocksPerB = (N + 255) / 256;
        if (blocksPerB > MAXBLK) blocksPerB = MAXBLK;
        reduce_solve_kernel<<<B * blocksPerB, 256>>>(pred, gt, w, N, blocksPerB);
        fused_kernel<<<B * ntri, NTHR>>>(pred, gt, w, ht, (float*)d_out,
                                         N, B, tilesI, ntri, 1);
    }
}

// round 13
// speedup vs baseline: 2.1231x; 1.1469x over previous
#include <cuda_runtime.h>
#include <math.h>

// ---------------------------------------------------------------------------
// DiffusionLoss fused single-kernel, fully warp-specialized:
//   blocks [0, B): SOLVER blocks — compute 18 moments over batch b (1024 thr,
//     coalesced), 3x3 Kabsch solve, closed-form bond term, AND the per-atom
//     alignment loss. All O(N) work lives here, concurrent with bond tiles.
//   blocks [B, B + B*ntri): TILE blocks — pure pairwise bond tiles
//     (upper-triangular, off-diag x2). No stats, no spins, no flags.
// Bond: sum_ij wiwj (dp-dg)^2 = [closed form O(N)] - 2*sum_ij wiwj dp*dg
//   -> O(N^2) loop computes only wi wj sqrt(|dp2*dg2|) (packed f32x2, 1 MUFU).
// No inter-block waiting anywhere -> safe for any grid size / multi-wave.
// Last block (global counter) combines + writes out + resets (replay-safe).
// ---------------------------------------------------------------------------

#define MAXB 16
#define TILE 256
#define NTHR 1024
#define NMOM 18

__device__ float    g_par[MAXB][15];   // R[9], mu[3], muGT[3]
__device__ double   g_W[MAXB];
__device__ double   g_closed[MAXB];    // closed-form sum_ij wiwj (dp2+dg2)
__device__ double   g_num1[MAXB];      // alignment numerator (solver-owned)
__device__ double   g_bond;            // sum_ij wi wj dp*dg (full matrix)
__device__ unsigned g_done;            // global arrival counter (wrap)

__device__ __forceinline__ float fsqrt_approx(float x) {
    float r;
    asm("sqrt.approx.f32 %0, %1;" : "=f"(r) : "f"(x));
    return r;
}

#define PACK_F32X2(out, lo, hi) \
    asm("mov.b64 %0, {%1, %2};" : "=l"(out) : "f"(lo), "f"(hi))
#define UNPACK_F32X2(lo, hi, in) \
    asm("mov.b64 {%0, %1}, %2;" : "=f"(lo), "=f"(hi) : "l"(in))
#define ADD_F32X2(out, a, b) \
    asm("add.rn.f32x2 %0, %1, %2;" : "=l"(out) : "l"(a), "l"(b))
#define FMA_F32X2(d, a, b, c) \
    asm("fma.rn.f32x2 %0, %1, %2, %3;" : "=l"(d) : "l"(a), "l"(b), "l"(c))

// ---------------------------------------------------------------------------
// 3x3 Kabsch solve from moments v[18]; also stores the closed-form term.
// ---------------------------------------------------------------------------
__device__ void kabsch_solve(const double* v, int b)
{
    double W = v[0];
    double invW = 1.0 / W;
    double spw2 = v[1]*v[1] + v[2]*v[2] + v[3]*v[3];
    double sgw2 = v[4]*v[4] + v[5]*v[5] + v[6]*v[6];
    g_closed[b] = 2.0*(W*v[16] - spw2) + 2.0*(W*v[17] - sgw2);

    // mu = GT weighted mean, muGT = pred mean (arg-swap in reference)
    float muGT[3] = { (float)(v[1]*invW), (float)(v[2]*invW), (float)(v[3]*invW) };
    float mu[3]   = { (float)(v[4]*invW), (float)(v[5]*invW), (float)(v[6]*invW) };

    float A[3][3];
    for (int i = 0; i < 3; i++)
        for (int j = 0; j < 3; j++)
            A[i][j] = (float)(v[7 + i*3 + j] - v[1+i]*v[4+j]*invW);

    float detA = A[0][0]*(A[1][1]*A[2][2]-A[1][2]*A[2][1])
               - A[0][1]*(A[1][0]*A[2][2]-A[1][2]*A[2][0])
               + A[0][2]*(A[1][0]*A[2][1]-A[1][1]*A[2][0]);

    float C[3][3];
    for (int i = 0; i < 3; i++)
        for (int j = 0; j < 3; j++) {
            float s = 0.f;
            for (int k = 0; k < 3; k++) s += A[k][i]*A[k][j];
            C[i][j] = s;
        }
    float V[3][3] = {{1,0,0},{0,1,0},{0,0,1}};
#pragma unroll
    for (int sweep = 0; sweep < 4; sweep++) {
#pragma unroll
        for (int p = 0; p < 3; p++)
#pragma unroll
            for (int q = p+1; q < 3; q++) {
                float apq = C[p][q];
                if (apq == 0.f) continue;
                float theta = __fdividef(C[q][q] - C[p][p], 2.f * apq);
                float tt = (theta >= 0.f ? 1.f : -1.f) *
                           __fdividef(1.f, fabsf(theta) + sqrtf(theta*theta + 1.f));
                float c = rsqrtf(tt*tt + 1.f), s = tt * c;
                for (int k = 0; k < 3; k++) {
                    float a = C[k][p], bb = C[k][q];
                    C[k][p] = c*a - s*bb;  C[k][q] = s*a + c*bb;
                }
                for (int k = 0; k < 3; k++) {
                    float a = C[p][k], bb = C[q][k];
                    C[p][k] = c*a - s*bb;  C[q][k] = s*a + c*bb;
                }
                for (int k = 0; k < 3; k++) {
                    float a = V[k][p], bb = V[k][q];
                    V[k][p] = c*a - s*bb;  V[k][q] = s*a + c*bb;
                }
            }
    }
    float eig[3] = { C[0][0], C[1][1], C[2][2] };
    int idx[3] = {0, 1, 2};
    for (int i = 0; i < 2; i++)
        for (int j = i+1; j < 3; j++)
            if (eig[idx[j]] > eig[idx[i]]) { int tmp = idx[i]; idx[i] = idx[j]; idx[j] = tmp; }

    float emax = fmaxf(eig[idx[0]], 0.f);
    float dinv[3];
    for (int i = 0; i < 3; i++) {
        float e = fmaxf(eig[idx[i]], 0.f);
        dinv[i] = (e > 1e-12f * emax && e > 0.f) ? rsqrtf(e) : 0.f;
    }
    if (detA < 0.f) dinv[2] = -dinv[2];

    float T[3][3];
    for (int i = 0; i < 3; i++)
        for (int j = 0; j < 3; j++) {
            float s = 0.f;
            for (int k = 0; k < 3; k++) s += A[i][k] * V[k][idx[j]];
            T[i][j] = s * dinv[j];
        }
    for (int i = 0; i < 3; i++)
        for (int j = 0; j < 3; j++) {
            float s = 0.f;
            for (int k = 0; k < 3; k++) s += T[i][k] * V[j][idx[k]];
            g_par[b][i*3 + j] = s;
        }
    g_par[b][9]  = mu[0];   g_par[b][10] = mu[1];   g_par[b][11] = mu[2];
    g_par[b][12] = muGT[0]; g_par[b][13] = muGT[1]; g_par[b][14] = muGT[2];
    g_W[b] = W;
}

// ---------------------------------------------------------------------------
// Shared completion epilogue: last arriving block combines + resets.
// ---------------------------------------------------------------------------
__device__ __forceinline__ void finish_and_maybe_combine(
    const float* __restrict__ ht, float* __restrict__ out, int B, unsigned grid)
{
    __threadfence();
    unsigned old = atomicInc(&g_done, grid - 1);
    if (old == grid - 1) {
        __threadfence();
        float sw = 0.f, sw2 = 0.f, sn = 0.f, scl = 0.f;
        for (int bb = 0; bb < B; bb++) {
            float W = (float)g_W[bb];
            sw += W; sw2 += W * W;
            sn += (float)g_num1[bb]; scl += (float)g_closed[bb];
        }
        float bond = (float)g_bond;
        float loss = __fdividef(sn, sw) + __fdividef(scl - 2.f * bond, sw2);
        for (int bb = 0; bb < B; bb++) {
            float h = __ldg(&ht[bb]);
            float d = (h + 16.f);
            out[bb] = (h*h + 256.f) * __fdividef(loss, d*d);
        }
        g_bond = 0.0;          // reset for next graph replay
        __threadfence();
    }
}

// ---------------------------------------------------------------------------
// Fused kernel (1024 threads).
// ---------------------------------------------------------------------------
__global__ void __launch_bounds__(NTHR)
fused_kernel(const float* __restrict__ pred,
             const float* __restrict__ gt,
             const float* __restrict__ w,
             const float* __restrict__ ht,
             float* __restrict__ out,
             int N, int B, int tilesI, int ntri)
{
    const int t   = threadIdx.x;
    const int blk = blockIdx.x;
    const unsigned mask = 0xffffffffu;
    const int warp = t >> 5, lane = t & 31;

    // ===================== SOLVER blocks =====================
    if (blk < B) {
        const int b = blk;
        const float* pb = pred + (size_t)b * N * 3;
        const float* gb = gt   + (size_t)b * N * 3;
        const float* wb = w    + (size_t)b * N;

        __shared__ float  smom[NTHR/32][NMOM];
        __shared__ double svv[NMOM];
        __shared__ float  sal[NTHR/32];

        // --- 18 moments, all 1024 threads, coalesced-ish row loads ---
        float acc[NMOM];
#pragma unroll
        for (int i = 0; i < NMOM; i++) acc[i] = 0.f;
        for (int n = t; n < N; n += NTHR) {
            float wn = wb[n];
            float px = pb[3*n], py = pb[3*n+1], pz = pb[3*n+2];
            float gx = gb[3*n], gy = gb[3*n+1], gz = gb[3*n+2];
            float wpx = wn*px, wpy = wn*py, wpz = wn*pz;
            acc[0] += wn;
            acc[1] += wpx;  acc[2] += wpy;  acc[3] += wpz;
            acc[4] += wn*gx; acc[5] += wn*gy; acc[6] += wn*gz;
            acc[7] += wpx*gx; acc[8] += wpx*gy; acc[9] += wpx*gz;
            acc[10] += wpy*gx; acc[11] += wpy*gy; acc[12] += wpy*gz;
            acc[13] += wpz*gx; acc[14] += wpz*gy; acc[15] += wpz*gz;
            acc[16] += wpx*px + wpy*py + wpz*pz;
            acc[17] += wn*(gx*gx + gy*gy + gz*gz);
        }
#pragma unroll
        for (int i = 0; i < NMOM; i++)
            for (int o = 16; o > 0; o >>= 1)
                acc[i] += __shfl_down_sync(mask, acc[i], o);
        if (lane == 0)
#pragma unroll
            for (int i = 0; i < NMOM; i++) smom[warp][i] = acc[i];
        __syncthreads();
        // threads 0..17 each gather one moment column (parallel, MLP)
        if (t < NMOM) {
            float s = 0.f;
            for (int k = 0; k < NTHR/32; k++) s += smom[k][t];
            svv[t] = (double)s;
        }
        __syncthreads();
        if (t == 0) kabsch_solve(svv, b);
        __syncthreads();   // g_par writes visible to block

        // --- alignment loss over all N atoms ---
        float R00 = g_par[b][0], R01 = g_par[b][1], R02 = g_par[b][2];
        float R10 = g_par[b][3], R11 = g_par[b][4], R12 = g_par[b][5];
        float R20 = g_par[b][6], R21 = g_par[b][7], R22 = g_par[b][8];
        float mux = g_par[b][9],  muy = g_par[b][10], muz = g_par[b][11];
        float mgx = g_par[b][12], mgy = g_par[b][13], mgz = g_par[b][14];

        float alf = 0.f;
        for (int n = t; n < N; n += NTHR) {
            float wn = wb[n];
            float gx = gb[3*n] - mux, gy = gb[3*n+1] - muy, gz = gb[3*n+2] - muz;
            float axv = R00*gx + R01*gy + R02*gz + mgx;
            float ayv = R10*gx + R11*gy + R12*gz + mgy;
            float azv = R20*gx + R21*gy + R22*gz + mgz;
            float dx = pb[3*n] - axv, dy = pb[3*n+1] - ayv, dz = pb[3*n+2] - azv;
            alf += wn * fsqrt_approx(dx*dx + dy*dy + dz*dz);
        }
        for (int o = 16; o > 0; o >>= 1)
            alf += __shfl_down_sync(mask, alf, o);
        if (lane == 0) sal[warp] = alf;
        __syncthreads();
        if (t == 0) {
            float s = 0.f;
            for (int k = 0; k < NTHR/32; k++) s += sal[k];
            g_num1[b] = (double)s;
            finish_and_maybe_combine(ht, out, B, gridDim.x);
        }
        return;
    }

    // ===================== TILE blocks =====================
    const int rp = t & 127;          // row-pair index (128 pairs = 256 rows)
    const int jq = t >> 7;           // j eighth 0..7 (32 j's each)

    int idx = blk - B;
    int b   = idx / ntri;
    int rem = idx % ntri;
    int ti = 0, rowlen = tilesI;
    while (rem >= rowlen) { rem -= rowlen; ti++; rowlen--; }
    int tj = ti + rem;
    const bool diag = (ti == tj);

    const float* pb = pred + (size_t)b * N * 3;
    const float* gb = gt   + (size_t)b * N * 3;
    const float* wb = w    + (size_t)b * N;

    __shared__ float rawPI[TILE*3], rawGI[TILE*3], rawWI[TILE];
    __shared__ float rawPJ[TILE*3], rawGJ[TILE*3], rawWJ[TILE];
    __shared__ float4 sA[TILE];   // (pjx, gjx, pjy, gjy)
    __shared__ float4 sZ[TILE];   // (pjz, gjz, pn2j, gn2j)
    __shared__ float  sW[TILE];
    __shared__ float  sredp[NTHR/32];

    // ---- stage tiles with coalesced LDG ----
    {
        int baseI3 = ti * TILE * 3, baseJ3 = tj * TILE * 3;
        int baseI = ti * TILE, baseJ = tj * TILE;
        int n3 = 3 * N;
        if (t < TILE*3) {
            int gi = baseI3 + t;
            float pv = 0.f, gv = 0.f;
            if (gi < n3) { pv = pb[gi]; gv = gb[gi]; }
            rawPI[t] = pv; rawGI[t] = gv;
        }
        if (t < TILE) {
            int gi = baseI + t;
            rawWI[t] = (gi < N) ? wb[gi] : 0.f;
        }
        if (!diag) {
            if (t < TILE*3) {
                int gi = baseJ3 + t;
                float pv = 0.f, gv = 0.f;
                if (gi < n3) { pv = pb[gi]; gv = gb[gi]; }
                rawPJ[t] = pv; rawGJ[t] = gv;
            }
            if (t < TILE) {
                int gi = baseJ + t;
                rawWJ[t] = (gi < N) ? wb[gi] : 0.f;
            }
        }
    }
    __syncthreads();

    const float* RPJ = diag ? rawPI : rawPJ;
    const float* RGJ = diag ? rawGI : rawGJ;
    const float* RWJ = diag ? rawWI : rawWJ;

    // ---- format j tile from smem (threads 0..255) ----
    if (t < TILE) {
        float px = RPJ[3*t], py = RPJ[3*t+1], pz = RPJ[3*t+2];
        float gx = RGJ[3*t], gy = RGJ[3*t+1], gz = RGJ[3*t+2];
        sA[t] = make_float4(px, gx, py, gy);
        sZ[t] = make_float4(pz, gz, px*px+py*py+pz*pz, gx*gx+gy*gy+gz*gz);
        sW[t] = RWJ[t];
    }

    // ---- load two i-rows into registers from smem ----
    float pxr[2], pyr[2], pzr[2], gxr[2], gyr[2], gzr[2], wr[2];
#pragma unroll
    for (int r = 0; r < 2; r++) {
        int li = 2*rp + r;
        pxr[r] = rawPI[3*li];   pyr[r] = rawPI[3*li+1]; pzr[r] = rawPI[3*li+2];
        gxr[r] = rawGI[3*li];   gyr[r] = rawGI[3*li+1]; gzr[r] = rawGI[3*li+2];
        wr[r]  = rawWI[li];
    }

    unsigned long long ax[2], ay[2], az[2], bs[2];
#pragma unroll
    for (int r = 0; r < 2; r++) {
        PACK_F32X2(ax[r], -2.f*pxr[r], -2.f*gxr[r]);
        PACK_F32X2(ay[r], -2.f*pyr[r], -2.f*gyr[r]);
        PACK_F32X2(az[r], -2.f*pzr[r], -2.f*gzr[r]);
        PACK_F32X2(bs[r], pxr[r]*pxr[r]+pyr[r]*pyr[r]+pzr[r]*pzr[r],
                          gxr[r]*gxr[r]+gyr[r]*gyr[r]+gzr[r]*gzr[r]);
    }
    __syncthreads();   // sA/sZ/sW visible

    // ---- cross-term loop: acc_r += wj * sqrt(|dp2*dg2|), 2 rows x 32 j ----
    float accr[2] = {0.f, 0.f};
    const int kbase = jq * 32;
#pragma unroll 4
    for (int kk = 0; kk < 32; kk++) {
        int k = kbase + kk;
        ulonglong2 A = *reinterpret_cast<const ulonglong2*>(&sA[k]);
        ulonglong2 Z = *reinterpret_cast<const ulonglong2*>(&sZ[k]);
        float wj = sW[k];
#pragma unroll
        for (int r = 0; r < 2; r++) {
            unsigned long long c;
            FMA_F32X2(c, az[r], Z.x, Z.y);   // -2z*zj + (pn2j,gn2j)
            FMA_F32X2(c, ay[r], A.y, c);
            FMA_F32X2(c, ax[r], A.x, c);
            ADD_F32X2(c, c, bs[r]);          // -> (dp2, dg2)
            float dp2, dg2;
            UNPACK_F32X2(dp2, dg2, c);
            float s = fsqrt_approx(fabsf(dp2 * dg2));  // |.| folds into MUFU
            accr[r] = fmaf(wj, s, accr[r]);
        }
    }

    float tot = accr[0]*wr[0] + accr[1]*wr[1];
    if (!diag) tot *= 2.f;           // symmetry
    for (int o = 16; o > 0; o >>= 1)
        tot += __shfl_down_sync(mask, tot, o);
    if (lane == 0) sredp[warp] = tot;
    __syncthreads();

    if (t == 0) {
        float s = 0.f;
        for (int wi = 0; wi < NTHR/32; wi++) s += sredp[wi];
        atomicAdd(&g_bond, (double)s);
        finish_and_maybe_combine(ht, out, B, gridDim.x);
    }
}

extern "C" void kernel_launch(void* const* d_in, const int* in_sizes, int n_in,
                              void* d_out, int out_size)
{
    const float* pred = (const float*)d_in[0];
    const float* gt   = (const float*)d_in[1];
    const float* ht   = (const float*)d_in[2];
    const float* w    = (const float*)d_in[3];
    int B = in_sizes[2];
    int N = in_sizes[3] / B;

    int tilesI = (N + TILE - 1) / TILE;
    int ntri = tilesI * (tilesI + 1) / 2;

    // No inter-block spins -> correct at any grid size (multi-wave safe).
    fused_kernel<<<B + B * ntri, NTHR>>>(pred, gt, w, ht, (float*)d_out,
                                         N, B, tilesI, ntri);
}